// round 1
// baseline (speedup 1.0000x reference)
#include <cuda_runtime.h>

#define HEADS 12
#define BATCH 8
#define NTOK  1024
#define HD    64
#define DIM   768
#define BHT   (BATCH*HEADS)   // 96

// Scratch (static __device__ globals — allocation-free per harness rules)
__device__ float g_q[BHT*NTOK*HD];        // 24 MB, per-head layout (bh, n, d)
__device__ float g_k[BHT*NTOK*HD];
__device__ float g_v[BHT*NTOK*HD];
__device__ float g_relh[BHT*NTOK*32];     // rel_h bias term
__device__ float g_relw[BHT*NTOK*32];     // rel_w bias term
__device__ float g_att[BATCH*NTOK*DIM];   // attention output, (b*1024+n, h*64+d)

// ---------------------------------------------------------------------------
// SGEMM: C(M,N) = A(M,K) @ B(N,K)^T + bias[N]
// EPI 0: A = x, scatter into g_q/g_k/g_v    (M=8192, N=2304, K=768)
// EPI 1: A = g_att, write C = d_out         (M=8192, N=768,  K=768)
// 128x128 block tile, BK=8, 256 threads, 8x8 microtile.
// ---------------------------------------------------------------------------
template<int EPI>
__global__ __launch_bounds__(256) void sgemm_kernel(
    const float* __restrict__ A, const float* __restrict__ B,
    const float* __restrict__ bias, float* __restrict__ C,
    int M, int N, int K)
{
  __shared__ __align__(16) float As[8][128];
  __shared__ __align__(16) float Bs[8][128];

  const int tid  = threadIdx.x;
  const int rowA = blockIdx.y * 128;
  const int colB = blockIdx.x * 128;
  const float* Ap = (EPI == 1) ? g_att : A;

  const int lr = tid >> 1;           // 0..127
  const int lk = (tid & 1) * 4;      // 0 or 4
  const int ty = tid >> 4;           // 0..15
  const int tx = tid & 15;           // 0..15

  float acc[8][8];
  #pragma unroll
  for (int i = 0; i < 8; i++)
    #pragma unroll
    for (int j = 0; j < 8; j++) acc[i][j] = 0.f;

  for (int kt = 0; kt < K; kt += 8) {
    float4 a4 = *reinterpret_cast<const float4*>(&Ap[(size_t)(rowA + lr) * K + kt + lk]);
    float4 b4 = *reinterpret_cast<const float4*>(&B [(size_t)(colB + lr) * K + kt + lk]);
    __syncthreads();
    As[lk+0][lr] = a4.x; As[lk+1][lr] = a4.y; As[lk+2][lr] = a4.z; As[lk+3][lr] = a4.w;
    Bs[lk+0][lr] = b4.x; Bs[lk+1][lr] = b4.y; Bs[lk+2][lr] = b4.z; Bs[lk+3][lr] = b4.w;
    __syncthreads();

    #pragma unroll
    for (int k = 0; k < 8; k++) {
      float4 av0 = *reinterpret_cast<const float4*>(&As[k][ty*8]);
      float4 av1 = *reinterpret_cast<const float4*>(&As[k][ty*8+4]);
      float4 bv0 = *reinterpret_cast<const float4*>(&Bs[k][tx*8]);
      float4 bv1 = *reinterpret_cast<const float4*>(&Bs[k][tx*8+4]);
      float a[8] = {av0.x, av0.y, av0.z, av0.w, av1.x, av1.y, av1.z, av1.w};
      float b[8] = {bv0.x, bv0.y, bv0.z, bv0.w, bv1.x, bv1.y, bv1.z, bv1.w};
      #pragma unroll
      for (int i = 0; i < 8; i++)
        #pragma unroll
        for (int j = 0; j < 8; j++) acc[i][j] += a[i] * b[j];
    }
  }

  #pragma unroll
  for (int i = 0; i < 8; i++) {
    const int r = rowA + ty*8 + i;
    #pragma unroll
    for (int j = 0; j < 8; j++) {
      const int c = colB + tx*8 + j;
      const float v = acc[i][j] + bias[c];
      if (EPI == 0) {
        const int which = c / DIM;            // 0=q 1=k 2=v
        const int hh    = (c % DIM) / HD;
        const int d     = c % HD;
        const int b     = r >> 10;
        const int n     = r & 1023;
        float* dst = (which == 0) ? g_q : ((which == 1) ? g_k : g_v);
        dst[((size_t)(b*HEADS + hh) * NTOK + n) * HD + d] = v;
      } else {
        C[(size_t)r * DIM + c] = v;
      }
    }
  }
}

// ---------------------------------------------------------------------------
// rel-pos bias pieces: rel_h[bh,n,kh] = q[bh,n,:] . rel_pos_h[qh-kh+31,:]
//                      rel_w[bh,n,kw] = q[bh,n,:] . rel_pos_w[qw-kw+31,:]
// (uses UNSCALED q, matching the reference)
// grid (256, 96), block 256: 4 tokens per block, 64 threads per token.
// ---------------------------------------------------------------------------
__global__ __launch_bounds__(256) void relpos_kernel(
    const float* __restrict__ rph, const float* __restrict__ rpw)
{
  const int bh  = blockIdx.y;
  const int g   = threadIdx.x >> 6;      // 0..3
  const int sub = threadIdx.x & 63;      // 0..63
  const int n   = blockIdx.x * 4 + g;

  __shared__ float qs[4][64];
  qs[g][sub] = g_q[((size_t)bh * NTOK + n) * HD + sub];
  __syncthreads();

  const int qh = n >> 5;
  const int qw = n & 31;
  const float* tbl;
  int row;
  float* out;
  if (sub < 32) {
    row = qh - sub + 31;
    tbl = rph;
    out = &g_relh[((size_t)bh * NTOK + n) * 32 + sub];
  } else {
    const int kw = sub - 32;
    row = qw - kw + 31;
    tbl = rpw;
    out = &g_relw[((size_t)bh * NTOK + n) * 32 + kw];
  }
  const float* t = tbl + row * HD;
  float acc = 0.f;
  #pragma unroll
  for (int c = 0; c < 64; c++) acc += qs[g][c] * t[c];
  *out = acc;
}

// ---------------------------------------------------------------------------
// Fused flash attention with decomposed rel-pos bias.
// grid (32 qtiles, 96 bh), block 256 = 8 warps; each warp owns 4 queries.
// Key tiles of 64 streamed through smem (pad 65 -> conflict-free row access).
// ---------------------------------------------------------------------------
__global__ __launch_bounds__(256) void attn_kernel()
{
  const int bh   = blockIdx.y;
  const int qt   = blockIdx.x;
  const int tid  = threadIdx.x;
  const int warp = tid >> 5;
  const int lane = tid & 31;

  __shared__ float Qs[32][65];
  __shared__ float Ks[64][65];
  __shared__ float Vs[64][65];

  const float scale = 0.125f;  // 64^-0.5

  const float* qb = g_q + ((size_t)bh * NTOK + qt * 32) * HD;
  for (int i = tid; i < 32*64; i += 256) Qs[i >> 6][i & 63] = qb[i] * scale;

  const int q0 = warp * 4;
  float m[4], l[4], acc0[4], acc1[4], rwv[4];
  #pragma unroll
  for (int qi = 0; qi < 4; qi++) {
    m[qi] = -1e30f; l[qi] = 0.f; acc0[qi] = 0.f; acc1[qi] = 0.f;
    const int n = qt * 32 + q0 + qi;
    rwv[qi] = g_relw[((size_t)bh * NTOK + n) * 32 + lane];  // kw == lane
  }

  for (int kt = 0; kt < 16; kt++) {
    __syncthreads();
    const float* kb = g_k + ((size_t)bh * NTOK + kt * 64) * HD;
    const float* vb = g_v + ((size_t)bh * NTOK + kt * 64) * HD;
    for (int i = tid; i < 64*64; i += 256) {
      const int r = i >> 6, c = i & 63;
      Ks[r][c] = kb[i];
      Vs[r][c] = vb[i];
    }
    __syncthreads();

    // ---- logits: this warp's lane covers keys (kt*64+lane) and (kt*64+lane+32)
    float d0[4], d1[4];
    #pragma unroll
    for (int qi = 0; qi < 4; qi++) { d0[qi] = 0.f; d1[qi] = 0.f; }
    #pragma unroll 8
    for (int d = 0; d < 64; d++) {
      const float k0 = Ks[lane][d];
      const float k1 = Ks[lane + 32][d];
      #pragma unroll
      for (int qi = 0; qi < 4; qi++) {
        const float qd = Qs[q0 + qi][d];
        d0[qi] += qd * k0;
        d1[qi] += qd * k1;
      }
    }

    // ---- bias + online softmax update
    float p0[4], p1[4];
    #pragma unroll
    for (int qi = 0; qi < 4; qi++) {
      const int n = qt * 32 + q0 + qi;
      const float* rh = g_relh + ((size_t)bh * NTOK + n) * 32 + 2 * kt;
      float l0 = d0[qi] + rh[0] + rwv[qi];   // key row kh = 2*kt   (keys lane)
      float l1 = d1[qi] + rh[1] + rwv[qi];   // key row kh = 2*kt+1 (keys lane+32)
      float tm = fmaxf(l0, l1);
      #pragma unroll
      for (int off = 16; off > 0; off >>= 1)
        tm = fmaxf(tm, __shfl_xor_sync(0xffffffffu, tm, off));
      const float mn   = fmaxf(m[qi], tm);
      const float corr = __expf(m[qi] - mn);
      p0[qi] = __expf(l0 - mn);
      p1[qi] = __expf(l1 - mn);
      float ps = p0[qi] + p1[qi];
      #pragma unroll
      for (int off = 16; off > 0; off >>= 1)
        ps += __shfl_xor_sync(0xffffffffu, ps, off);
      l[qi]    = l[qi] * corr + ps;
      acc0[qi] *= corr;
      acc1[qi] *= corr;
      m[qi]    = mn;
    }

    // ---- PV: lane owns output dims d=lane and d=lane+32
    #pragma unroll 4
    for (int k = 0; k < 32; k++) {
      const float v0 = Vs[k][lane];
      const float v1 = Vs[k][lane + 32];
      #pragma unroll
      for (int qi = 0; qi < 4; qi++) {
        const float pk = __shfl_sync(0xffffffffu, p0[qi], k);
        acc0[qi] += pk * v0;
        acc1[qi] += pk * v1;
      }
    }
    #pragma unroll 4
    for (int k = 0; k < 32; k++) {
      const float v0 = Vs[k + 32][lane];
      const float v1 = Vs[k + 32][lane + 32];
      #pragma unroll
      for (int qi = 0; qi < 4; qi++) {
        const float pk = __shfl_sync(0xffffffffu, p1[qi], k);
        acc0[qi] += pk * v0;
        acc1[qi] += pk * v1;
      }
    }
  }

  const int b = bh / HEADS, h = bh % HEADS;
  #pragma unroll
  for (int qi = 0; qi < 4; qi++) {
    const int n = qt * 32 + q0 + qi;
    const float inv = 1.f / l[qi];
    float* o = g_att + ((size_t)(b * NTOK) + n) * DIM + h * HD;
    o[lane]      = acc0[qi] * inv;
    o[lane + 32] = acc1[qi] * inv;
  }
}

// ---------------------------------------------------------------------------
extern "C" void kernel_launch(void* const* d_in, const int* in_sizes, int n_in,
                              void* d_out, int out_size)
{
  const float* x      = (const float*)d_in[0];
  const float* qkv_w  = (const float*)d_in[1];
  const float* qkv_b  = (const float*)d_in[2];
  const float* proj_w = (const float*)d_in[3];
  const float* proj_b = (const float*)d_in[4];
  const float* rph    = (const float*)d_in[5];
  const float* rpw    = (const float*)d_in[6];
  float* out = (float*)d_out;

  // 1) QKV projection + per-head scatter
  dim3 g1(2304 / 128, 8192 / 128);
  sgemm_kernel<0><<<g1, 256>>>(x, qkv_w, qkv_b, nullptr, 8192, 2304, 768);

  // 2) decomposed rel-pos bias terms
  relpos_kernel<<<dim3(256, 96), 256>>>(rph, rpw);

  // 3) fused attention (flash-style, bias folded in)
  attn_kernel<<<dim3(32, 96), 256>>>();

  // 4) output projection
  dim3 g2(768 / 128, 8192 / 128);
  sgemm_kernel<1><<<g2, 256>>>(nullptr, proj_w, proj_b, out, 8192, 768, 768);
}

// round 2
// speedup vs baseline: 1.0004x; 1.0004x over previous
#include <cuda_runtime.h>

#define HEADS 12
#define BATCH 8
#define NTOK  1024
#define HD    64
#define DIM   768
#define BHT   (BATCH*HEADS)   // 96

// Scratch (static __device__ globals — allocation-free per harness rules)
__device__ float g_q[BHT*NTOK*HD];        // 24 MB, per-head layout (bh, n, d)
__device__ float g_k[BHT*NTOK*HD];
__device__ float g_v[BHT*NTOK*HD];
__device__ float g_relh[BHT*NTOK*32];     // rel_h bias term
__device__ float g_relw[BHT*NTOK*32];     // rel_w bias term
__device__ float g_att[BATCH*NTOK*DIM];   // attention output, (b*1024+n, h*64+d)

// ---------------------------------------------------------------------------
// SGEMM: C(M,N) = A(M,K) @ B(N,K)^T + bias[N]
// EPI 0: A = x, scatter into g_q/g_k/g_v    (M=8192, N=2304, K=768)
// EPI 1: A = g_att, write C = d_out         (M=8192, N=768,  K=768)
// 128x128 block tile, BK=8, 256 threads, 8x8 microtile.
// ---------------------------------------------------------------------------
template<int EPI>
__global__ __launch_bounds__(256) void sgemm_kernel(
    const float* __restrict__ A, const float* __restrict__ B,
    const float* __restrict__ bias, float* __restrict__ C,
    int M, int N, int K)
{
  __shared__ __align__(16) float As[8][128];
  __shared__ __align__(16) float Bs[8][128];

  const int tid  = threadIdx.x;
  const int rowA = blockIdx.y * 128;
  const int colB = blockIdx.x * 128;
  const float* Ap = (EPI == 1) ? g_att : A;

  const int lr = tid >> 1;           // 0..127
  const int lk = (tid & 1) * 4;      // 0 or 4
  const int ty = tid >> 4;           // 0..15
  const int tx = tid & 15;           // 0..15

  float acc[8][8];
  #pragma unroll
  for (int i = 0; i < 8; i++)
    #pragma unroll
    for (int j = 0; j < 8; j++) acc[i][j] = 0.f;

  for (int kt = 0; kt < K; kt += 8) {
    float4 a4 = *reinterpret_cast<const float4*>(&Ap[(size_t)(rowA + lr) * K + kt + lk]);
    float4 b4 = *reinterpret_cast<const float4*>(&B [(size_t)(colB + lr) * K + kt + lk]);
    __syncthreads();
    As[lk+0][lr] = a4.x; As[lk+1][lr] = a4.y; As[lk+2][lr] = a4.z; As[lk+3][lr] = a4.w;
    Bs[lk+0][lr] = b4.x; Bs[lk+1][lr] = b4.y; Bs[lk+2][lr] = b4.z; Bs[lk+3][lr] = b4.w;
    __syncthreads();

    #pragma unroll
    for (int k = 0; k < 8; k++) {
      float4 av0 = *reinterpret_cast<const float4*>(&As[k][ty*8]);
      float4 av1 = *reinterpret_cast<const float4*>(&As[k][ty*8+4]);
      float4 bv0 = *reinterpret_cast<const float4*>(&Bs[k][tx*8]);
      float4 bv1 = *reinterpret_cast<const float4*>(&Bs[k][tx*8+4]);
      float a[8] = {av0.x, av0.y, av0.z, av0.w, av1.x, av1.y, av1.z, av1.w};
      float b[8] = {bv0.x, bv0.y, bv0.z, bv0.w, bv1.x, bv1.y, bv1.z, bv1.w};
      #pragma unroll
      for (int i = 0; i < 8; i++)
        #pragma unroll
        for (int j = 0; j < 8; j++) acc[i][j] += a[i] * b[j];
    }
  }

  #pragma unroll
  for (int i = 0; i < 8; i++) {
    const int r = rowA + ty*8 + i;
    #pragma unroll
    for (int j = 0; j < 8; j++) {
      const int c = colB + tx*8 + j;
      const float v = acc[i][j] + bias[c];
      if (EPI == 0) {
        const int which = c / DIM;            // 0=q 1=k 2=v
        const int hh    = (c % DIM) / HD;
        const int d     = c % HD;
        const int b     = r >> 10;
        const int n     = r & 1023;
        float* dst = (which == 0) ? g_q : ((which == 1) ? g_k : g_v);
        dst[((size_t)(b*HEADS + hh) * NTOK + n) * HD + d] = v;
      } else {
        C[(size_t)r * DIM + c] = v;
      }
    }
  }
}

// ---------------------------------------------------------------------------
// rel-pos bias pieces: rel_h[bh,n,kh] = q[bh,n,:] . rel_pos_h[qh-kh+31,:]
//                      rel_w[bh,n,kw] = q[bh,n,:] . rel_pos_w[qw-kw+31,:]
// (uses UNSCALED q, matching the reference)
// grid (256, 96), block 256: 4 tokens per block, 64 threads per token.
// ---------------------------------------------------------------------------
__global__ __launch_bounds__(256) void relpos_kernel(
    const float* __restrict__ rph, const float* __restrict__ rpw)
{
  const int bh  = blockIdx.y;
  const int g   = threadIdx.x >> 6;      // 0..3
  const int sub = threadIdx.x & 63;      // 0..63
  const int n   = blockIdx.x * 4 + g;

  __shared__ float qs[4][64];
  qs[g][sub] = g_q[((size_t)bh * NTOK + n) * HD + sub];
  __syncthreads();

  const int qh = n >> 5;
  const int qw = n & 31;
  const float* tbl;
  int row;
  float* out;
  if (sub < 32) {
    row = qh - sub + 31;
    tbl = rph;
    out = &g_relh[((size_t)bh * NTOK + n) * 32 + sub];
  } else {
    const int kw = sub - 32;
    row = qw - kw + 31;
    tbl = rpw;
    out = &g_relw[((size_t)bh * NTOK + n) * 32 + kw];
  }
  const float* t = tbl + row * HD;
  float acc = 0.f;
  #pragma unroll
  for (int c = 0; c < 64; c++) acc += qs[g][c] * t[c];
  *out = acc;
}

// ---------------------------------------------------------------------------
// Fused flash attention with decomposed rel-pos bias.
// grid (32 qtiles, 96 bh), block 256 = 8 warps; each warp owns 4 queries.
// Key tiles of 64 streamed through smem (pad 65 -> conflict-free row access).
// ---------------------------------------------------------------------------
__global__ __launch_bounds__(256) void attn_kernel()
{
  const int bh   = blockIdx.y;
  const int qt   = blockIdx.x;
  const int tid  = threadIdx.x;
  const int warp = tid >> 5;
  const int lane = tid & 31;

  __shared__ float Qs[32][65];
  __shared__ float Ks[64][65];
  __shared__ float Vs[64][65];

  const float scale = 0.125f;  // 64^-0.5

  const float* qb = g_q + ((size_t)bh * NTOK + qt * 32) * HD;
  for (int i = tid; i < 32*64; i += 256) Qs[i >> 6][i & 63] = qb[i] * scale;

  const int q0 = warp * 4;
  float m[4], l[4], acc0[4], acc1[4], rwv[4];
  #pragma unroll
  for (int qi = 0; qi < 4; qi++) {
    m[qi] = -1e30f; l[qi] = 0.f; acc0[qi] = 0.f; acc1[qi] = 0.f;
    const int n = qt * 32 + q0 + qi;
    rwv[qi] = g_relw[((size_t)bh * NTOK + n) * 32 + lane];  // kw == lane
  }

  for (int kt = 0; kt < 16; kt++) {
    __syncthreads();
    const float* kb = g_k + ((size_t)bh * NTOK + kt * 64) * HD;
    const float* vb = g_v + ((size_t)bh * NTOK + kt * 64) * HD;
    for (int i = tid; i < 64*64; i += 256) {
      const int r = i >> 6, c = i & 63;
      Ks[r][c] = kb[i];
      Vs[r][c] = vb[i];
    }
    __syncthreads();

    // ---- logits: this warp's lane covers keys (kt*64+lane) and (kt*64+lane+32)
    float d0[4], d1[4];
    #pragma unroll
    for (int qi = 0; qi < 4; qi++) { d0[qi] = 0.f; d1[qi] = 0.f; }
    #pragma unroll 8
    for (int d = 0; d < 64; d++) {
      const float k0 = Ks[lane][d];
      const float k1 = Ks[lane + 32][d];
      #pragma unroll
      for (int qi = 0; qi < 4; qi++) {
        const float qd = Qs[q0 + qi][d];
        d0[qi] += qd * k0;
        d1[qi] += qd * k1;
      }
    }

    // ---- bias + online softmax update
    float p0[4], p1[4];
    #pragma unroll
    for (int qi = 0; qi < 4; qi++) {
      const int n = qt * 32 + q0 + qi;
      const float* rh = g_relh + ((size_t)bh * NTOK + n) * 32 + 2 * kt;
      float l0 = d0[qi] + rh[0] + rwv[qi];   // key row kh = 2*kt   (keys lane)
      float l1 = d1[qi] + rh[1] + rwv[qi];   // key row kh = 2*kt+1 (keys lane+32)
      float tm = fmaxf(l0, l1);
      #pragma unroll
      for (int off = 16; off > 0; off >>= 1)
        tm = fmaxf(tm, __shfl_xor_sync(0xffffffffu, tm, off));
      const float mn   = fmaxf(m[qi], tm);
      const float corr = __expf(m[qi] - mn);
      p0[qi] = __expf(l0 - mn);
      p1[qi] = __expf(l1 - mn);
      float ps = p0[qi] + p1[qi];
      #pragma unroll
      for (int off = 16; off > 0; off >>= 1)
        ps += __shfl_xor_sync(0xffffffffu, ps, off);
      l[qi]    = l[qi] * corr + ps;
      acc0[qi] *= corr;
      acc1[qi] *= corr;
      m[qi]    = mn;
    }

    // ---- PV: lane owns output dims d=lane and d=lane+32
    #pragma unroll 4
    for (int k = 0; k < 32; k++) {
      const float v0 = Vs[k][lane];
      const float v1 = Vs[k][lane + 32];
      #pragma unroll
      for (int qi = 0; qi < 4; qi++) {
        const float pk = __shfl_sync(0xffffffffu, p0[qi], k);
        acc0[qi] += pk * v0;
        acc1[qi] += pk * v1;
      }
    }
    #pragma unroll 4
    for (int k = 0; k < 32; k++) {
      const float v0 = Vs[k + 32][lane];
      const float v1 = Vs[k + 32][lane + 32];
      #pragma unroll
      for (int qi = 0; qi < 4; qi++) {
        const float pk = __shfl_sync(0xffffffffu, p1[qi], k);
        acc0[qi] += pk * v0;
        acc1[qi] += pk * v1;
      }
    }
  }

  const int b = bh / HEADS, h = bh % HEADS;
  #pragma unroll
  for (int qi = 0; qi < 4; qi++) {
    const int n = qt * 32 + q0 + qi;
    const float inv = 1.f / l[qi];
    float* o = g_att + ((size_t)(b * NTOK) + n) * DIM + h * HD;
    o[lane]      = acc0[qi] * inv;
    o[lane + 32] = acc1[qi] * inv;
  }
}

// ---------------------------------------------------------------------------
extern "C" void kernel_launch(void* const* d_in, const int* in_sizes, int n_in,
                              void* d_out, int out_size)
{
  const float* x      = (const float*)d_in[0];
  const float* qkv_w  = (const float*)d_in[1];
  const float* qkv_b  = (const float*)d_in[2];
  const float* proj_w = (const float*)d_in[3];
  const float* proj_b = (const float*)d_in[4];
  const float* rph    = (const float*)d_in[5];
  const float* rpw    = (const float*)d_in[6];
  float* out = (float*)d_out;

  // 1) QKV projection + per-head scatter
  dim3 g1(2304 / 128, 8192 / 128);
  sgemm_kernel<0><<<g1, 256>>>(x, qkv_w, qkv_b, nullptr, 8192, 2304, 768);

  // 2) decomposed rel-pos bias terms
  relpos_kernel<<<dim3(256, 96), 256>>>(rph, rpw);

  // 3) fused attention (flash-style, bias folded in)
  attn_kernel<<<dim3(32, 96), 256>>>();

  // 4) output projection
  dim3 g2(768 / 128, 8192 / 128);
  sgemm_kernel<1><<<g2, 256>>>(nullptr, proj_w, proj_b, out, 8192, 768, 768);
}

// round 3
// speedup vs baseline: 1.6822x; 1.6815x over previous
#include <cuda_runtime.h>
#include <cuda_bf16.h>

#define HEADS 12
#define NTOK  1024
#define HD    64
#define DIM   768
#define BHT   96
#define MTOT  8192

__device__ __align__(16) __nv_bfloat16 g_xh[MTOT*DIM],  g_xl[MTOT*DIM];
__device__ __align__(16) __nv_bfloat16 g_wh[2304*DIM],  g_wl[2304*DIM];
__device__ __align__(16) __nv_bfloat16 g_pwh[DIM*DIM],  g_pwl[DIM*DIM];
__device__ __align__(16) __nv_bfloat16 g_qh[BHT*NTOK*HD], g_ql[BHT*NTOK*HD];
__device__ __align__(16) __nv_bfloat16 g_kh[BHT*NTOK*HD], g_kl[BHT*NTOK*HD];
__device__ __align__(16) __nv_bfloat16 g_vh[BHT*NTOK*HD], g_vl[BHT*NTOK*HD];
__device__ __align__(16) __nv_bfloat16 g_ah[MTOT*DIM],  g_al[MTOT*DIM];
__device__ float g_relh[BHT*NTOK*32];
__device__ float g_relw[BHT*NTOK*32];

__device__ __forceinline__ void mma16816(float* c, const unsigned* a, const unsigned* b) {
  asm volatile(
    "mma.sync.aligned.m16n8k16.row.col.f32.bf16.bf16.f32 "
    "{%0,%1,%2,%3}, {%4,%5,%6,%7}, {%8,%9}, {%0,%1,%2,%3};\n"
    : "+f"(c[0]), "+f"(c[1]), "+f"(c[2]), "+f"(c[3])
    : "r"(a[0]), "r"(a[1]), "r"(a[2]), "r"(a[3]), "r"(b[0]), "r"(b[1]));
}
__device__ __forceinline__ unsigned pack2(float a, float b) {
  __nv_bfloat162 t = __floats2bfloat162_rn(a, b);
  return *reinterpret_cast<unsigned*>(&t);
}
__device__ __forceinline__ float bf16hi(float v) {
  return __bfloat162float(__float2bfloat16(v));
}
__device__ __forceinline__ unsigned pick2(const __nv_bfloat16* s, int i0, int i1) {
  unsigned a = *reinterpret_cast<const unsigned short*>(&s[i0]);
  unsigned b = *reinterpret_cast<const unsigned short*>(&s[i1]);
  return a | (b << 16);
}

// fp32 -> bf16 hi/lo split. W: 0=x 1=qkv_w 2=proj_w
template<int W>
__global__ void split_kernel(const float* __restrict__ src, int n) {
  int i = blockIdx.x * 256 + threadIdx.x;
  if (i >= n) return;
  __nv_bfloat16* h = (W==0) ? g_xh : (W==1) ? g_wh : g_pwh;
  __nv_bfloat16* l = (W==0) ? g_xl : (W==1) ? g_wl : g_pwl;
  float v = src[i];
  __nv_bfloat16 hb = __float2bfloat16(v);
  h[i] = hb;
  l[i] = __float2bfloat16(v - __bfloat162float(hb));
}

// C(M,N)=A(M,768)@B(N,768)^T + bias. tile 128x64, 256 thr, 8 warps 4x2.
// EPI0: A=x B=qkv_w -> scatter q/k/v hi/lo. EPI1: A=att B=proj_w -> fp32 out.
template<int EPI>
__global__ __launch_bounds__(256, 2) void gemm3bf16(const float* __restrict__ bias,
                                                    float* __restrict__ out) {
  __shared__ unsigned sA_h[128*20], sA_l[128*20], sB_h[64*20], sB_l[64*20];
  const int tid = threadIdx.x, lane = tid & 31, warp = tid >> 5;
  const int wm = warp >> 1, wn = warp & 1;
  const int gr = lane >> 2, tg = lane & 3;
  const int rowA = blockIdx.y * 128, colB = blockIdx.x * 64;

  const unsigned* gAh = reinterpret_cast<const unsigned*>(EPI ? g_ah : g_xh);
  const unsigned* gAl = reinterpret_cast<const unsigned*>(EPI ? g_al : g_xl);
  const unsigned* gBh = reinterpret_cast<const unsigned*>(EPI ? g_pwh : g_wh);
  const unsigned* gBl = reinterpret_cast<const unsigned*>(EPI ? g_pwl : g_wl);

  float acc[2][4][4];
  #pragma unroll
  for (int m = 0; m < 2; m++)
    #pragma unroll
    for (int n = 0; n < 4; n++)
      #pragma unroll
      for (int e = 0; e < 4; e++) acc[m][n][e] = 0.f;

  for (int kt = 0; kt < DIM; kt += 32) {
    __syncthreads();
    #pragma unroll
    for (int i = tid; i < 128*16; i += 256) {
      int r = i >> 4, c = i & 15;
      size_t g = (size_t)(rowA + r) * 384 + (kt >> 1) + c;
      sA_h[r*20 + c] = gAh[g];
      sA_l[r*20 + c] = gAl[g];
    }
    #pragma unroll
    for (int i = tid; i < 64*16; i += 256) {
      int r = i >> 4, c = i & 15;
      size_t g = (size_t)(colB + r) * 384 + (kt >> 1) + c;
      sB_h[r*20 + c] = gBh[g];
      sB_l[r*20 + c] = gBl[g];
    }
    __syncthreads();

    #pragma unroll
    for (int ks = 0; ks < 2; ks++) {
      const int kw = ks * 8;
      unsigned a_h[2][4], a_l[2][4];
      #pragma unroll
      for (int mt = 0; mt < 2; mt++) {
        int r = wm*32 + mt*16 + gr;
        a_h[mt][0] = sA_h[r*20+kw+tg];   a_h[mt][1] = sA_h[(r+8)*20+kw+tg];
        a_h[mt][2] = sA_h[r*20+kw+4+tg]; a_h[mt][3] = sA_h[(r+8)*20+kw+4+tg];
        a_l[mt][0] = sA_l[r*20+kw+tg];   a_l[mt][1] = sA_l[(r+8)*20+kw+tg];
        a_l[mt][2] = sA_l[r*20+kw+4+tg]; a_l[mt][3] = sA_l[(r+8)*20+kw+4+tg];
      }
      #pragma unroll
      for (int nt = 0; nt < 4; nt++) {
        int n = wn*32 + nt*8 + gr;
        unsigned bh[2] = { sB_h[n*20+kw+tg], sB_h[n*20+kw+4+tg] };
        unsigned bl[2] = { sB_l[n*20+kw+tg], sB_l[n*20+kw+4+tg] };
        #pragma unroll
        for (int mt = 0; mt < 2; mt++) {
          mma16816(acc[mt][nt], a_h[mt], bh);
          mma16816(acc[mt][nt], a_h[mt], bl);
          mma16816(acc[mt][nt], a_l[mt], bh);
        }
      }
    }
  }

  if (EPI == 0) {
    const int which = colB / DIM, head = (colB % DIM) / HD;
    __nv_bfloat16* dh = (which==0) ? g_qh : (which==1) ? g_kh : g_vh;
    __nv_bfloat16* dl = (which==0) ? g_ql : (which==1) ? g_kl : g_vl;
    #pragma unroll
    for (int mt = 0; mt < 2; mt++) {
      int r = rowA + wm*32 + mt*16 + gr;
      int b = r >> 10, n = r & 1023;
      size_t base = ((size_t)(b*HEADS + head) * NTOK + n) * HD;
      #pragma unroll
      for (int nt = 0; nt < 4; nt++) {
        int d0 = wn*32 + nt*8 + tg*2;
        float b0 = bias[colB+d0], b1 = bias[colB+d0+1];
        float v0 = acc[mt][nt][0]+b0, v1 = acc[mt][nt][1]+b1;
        float v2 = acc[mt][nt][2]+b0, v3 = acc[mt][nt][3]+b1;
        float h0 = bf16hi(v0), h1 = bf16hi(v1), h2 = bf16hi(v2), h3 = bf16hi(v3);
        *reinterpret_cast<unsigned*>(&dh[base+d0])        = pack2(h0, h1);
        *reinterpret_cast<unsigned*>(&dl[base+d0])        = pack2(v0-h0, v1-h1);
        *reinterpret_cast<unsigned*>(&dh[base+8*HD+d0])   = pack2(h2, h3);
        *reinterpret_cast<unsigned*>(&dl[base+8*HD+d0])   = pack2(v2-h2, v3-h3);
      }
    }
  } else {
    #pragma unroll
    for (int mt = 0; mt < 2; mt++) {
      int r = rowA + wm*32 + mt*16 + gr;
      #pragma unroll
      for (int nt = 0; nt < 4; nt++) {
        int c0 = colB + wn*32 + nt*8 + tg*2;
        float b0 = bias[c0], b1 = bias[c0+1];
        float2 v;
        v.x = acc[mt][nt][0]+b0; v.y = acc[mt][nt][1]+b1;
        *reinterpret_cast<float2*>(&out[(size_t)r*DIM + c0]) = v;
        v.x = acc[mt][nt][2]+b0; v.y = acc[mt][nt][3]+b1;
        *reinterpret_cast<float2*>(&out[(size_t)(r+8)*DIM + c0]) = v;
      }
    }
  }
}

// rel-pos dot products from reconstructed q
__global__ __launch_bounds__(256) void relpos_kernel(
    const float* __restrict__ rph, const float* __restrict__ rpw) {
  const int bh = blockIdx.y, g = threadIdx.x >> 6, sub = threadIdx.x & 63;
  const int n = blockIdx.x * 4 + g;
  __shared__ float qs[4][64];
  {
    size_t i = ((size_t)bh * NTOK + n) * HD + sub;
    qs[g][sub] = __bfloat162float(g_qh[i]) + __bfloat162float(g_ql[i]);
  }
  __syncthreads();
  const int qh = n >> 5, qw = n & 31;
  const float* tbl; int row; float* o;
  if (sub < 32) {
    row = qh - sub + 31; tbl = rph;
    o = &g_relh[((size_t)bh*NTOK + n)*32 + sub];
  } else {
    int kw = sub - 32;
    row = qw - kw + 31; tbl = rpw;
    o = &g_relw[((size_t)bh*NTOK + n)*32 + kw];
  }
  const float* t = tbl + row*HD;
  float a = 0.f;
  #pragma unroll
  for (int c = 0; c < 64; c++) a += qs[g][c] * t[c];
  *o = a;
}

// fused attention: grid(16,96), 128 thr = 4 warps, warp = 16 q rows.
// no-max softmax (bounded logits). dynamic smem 72192B.
__global__ __launch_bounds__(128) void attn_kernel() {
  extern __shared__ unsigned sm[];
  unsigned* sQh = sm;            unsigned* sQl = sQh + 2304;
  unsigned* sKh = sQl + 2304;    unsigned* sKl = sKh + 2304;
  unsigned* sVh = sKl + 2304;    unsigned* sVl = sVh + 2304;
  float* sRh = (float*)(sVl + 2304);
  float* sRw = sRh + 2112;

  const int bh = blockIdx.y, qt = blockIdx.x, tid = threadIdx.x;
  const int lane = tid & 31, wq = tid >> 5;
  const int gr = lane >> 2, tg = lane & 3;

  {
    const unsigned* gQh = reinterpret_cast<const unsigned*>(g_qh);
    const unsigned* gQl = reinterpret_cast<const unsigned*>(g_ql);
    size_t qb = ((size_t)bh*NTOK + qt*64) * 32;
    size_t rb = ((size_t)bh*NTOK + qt*64) * 32;
    #pragma unroll
    for (int i = tid; i < 2048; i += 128) {
      int r = i >> 5, c = i & 31;
      sQh[r*36+c] = gQh[qb+i];
      sQl[r*36+c] = gQl[qb+i];
      sRh[r*33+c] = g_relh[rb+i];
      sRw[r*33+c] = g_relw[rb+i];
    }
  }

  float oacc[8][4];
  #pragma unroll
  for (int n = 0; n < 8; n++)
    #pragma unroll
    for (int e = 0; e < 4; e++) oacc[n][e] = 0.f;
  float rs0 = 0.f, rs1 = 0.f;
  const int rq0 = wq*16 + gr;

  for (int kt = 0; kt < 16; kt++) {
    __syncthreads();
    {
      const unsigned* gKh = reinterpret_cast<const unsigned*>(g_kh);
      const unsigned* gKl = reinterpret_cast<const unsigned*>(g_kl);
      const unsigned* gVh = reinterpret_cast<const unsigned*>(g_vh);
      const unsigned* gVl = reinterpret_cast<const unsigned*>(g_vl);
      size_t kb = ((size_t)bh*NTOK + kt*64) * 32;
      #pragma unroll
      for (int i = tid; i < 2048; i += 128) {
        int r = i >> 5, c = i & 31;
        sKh[r*36+c] = gKh[kb+i];
        sKl[r*36+c] = gKl[kb+i];
        sVh[r*36+c] = gVh[kb+i];
        sVl[r*36+c] = gVl[kb+i];
      }
    }
    __syncthreads();

    float sacc[8][4];
    #pragma unroll
    for (int j = 0; j < 8; j++)
      #pragma unroll
      for (int e = 0; e < 4; e++) sacc[j][e] = 0.f;

    #pragma unroll
    for (int kk = 0; kk < 4; kk++) {
      const int kw = kk * 8;
      unsigned qa_h[4], qa_l[4];
      qa_h[0] = sQh[rq0*36+kw+tg];   qa_h[1] = sQh[(rq0+8)*36+kw+tg];
      qa_h[2] = sQh[rq0*36+kw+4+tg]; qa_h[3] = sQh[(rq0+8)*36+kw+4+tg];
      qa_l[0] = sQl[rq0*36+kw+tg];   qa_l[1] = sQl[(rq0+8)*36+kw+tg];
      qa_l[2] = sQl[rq0*36+kw+4+tg]; qa_l[3] = sQl[(rq0+8)*36+kw+4+tg];
      #pragma unroll
      for (int j = 0; j < 8; j++) {
        int n = j*8 + gr;
        unsigned kb2[2] = { sKh[n*36+kw+tg], sKh[n*36+kw+4+tg] };
        unsigned kl2[2] = { sKl[n*36+kw+tg], sKl[n*36+kw+4+tg] };
        mma16816(sacc[j], qa_h, kb2);
        mma16816(sacc[j], qa_h, kl2);
        mma16816(sacc[j], qa_l, kb2);
      }
    }

    unsigned phi[4][4], plo[4][4];
    #pragma unroll
    for (int j = 0; j < 8; j++) {
      int kh  = kt*2 + (j >> 2);
      int kw0 = (j & 3)*8 + tg*2;
      float rh0 = sRh[rq0*33+kh], rh1 = sRh[(rq0+8)*33+kh];
      float e0 = __expf(fmaf(0.125f, sacc[j][0], rh0 + sRw[rq0*33+kw0]));
      float e1 = __expf(fmaf(0.125f, sacc[j][1], rh0 + sRw[rq0*33+kw0+1]));
      float e2 = __expf(fmaf(0.125f, sacc[j][2], rh1 + sRw[(rq0+8)*33+kw0]));
      float e3 = __expf(fmaf(0.125f, sacc[j][3], rh1 + sRw[(rq0+8)*33+kw0+1]));
      rs0 += e0 + e1;
      rs1 += e2 + e3;
      float h0 = bf16hi(e0), h1 = bf16hi(e1), h2 = bf16hi(e2), h3 = bf16hi(e3);
      phi[j>>1][(j&1)*2]   = pack2(h0, h1);
      phi[j>>1][(j&1)*2+1] = pack2(h2, h3);
      plo[j>>1][(j&1)*2]   = pack2(e0-h0, e1-h1);
      plo[j>>1][(j&1)*2+1] = pack2(e2-h2, e3-h3);
    }

    const __nv_bfloat16* vh16 = reinterpret_cast<const __nv_bfloat16*>(sVh);
    const __nv_bfloat16* vl16 = reinterpret_cast<const __nv_bfloat16*>(sVl);
    #pragma unroll
    for (int j16 = 0; j16 < 4; j16++) {
      const int k0 = j16*16 + tg*2;
      #pragma unroll
      for (int nt = 0; nt < 8; nt++) {
        int d = nt*8 + gr;
        unsigned vbh[2] = { pick2(vh16, k0*72+d,     (k0+1)*72+d),
                            pick2(vh16, (k0+8)*72+d, (k0+9)*72+d) };
        unsigned vbl[2] = { pick2(vl16, k0*72+d,     (k0+1)*72+d),
                            pick2(vl16, (k0+8)*72+d, (k0+9)*72+d) };
        mma16816(oacc[nt], phi[j16], vbh);
        mma16816(oacc[nt], phi[j16], vbl);
        mma16816(oacc[nt], plo[j16], vbh);
      }
    }
  }

  rs0 += __shfl_xor_sync(0xffffffffu, rs0, 1);
  rs0 += __shfl_xor_sync(0xffffffffu, rs0, 2);
  rs1 += __shfl_xor_sync(0xffffffffu, rs1, 1);
  rs1 += __shfl_xor_sync(0xffffffffu, rs1, 2);
  const float inv0 = 1.f / rs0, inv1 = 1.f / rs1;

  const int b = bh / HEADS, head = bh % HEADS;
  const int n0 = qt*64 + wq*16 + gr;
  #pragma unroll
  for (int nt = 0; nt < 8; nt++) {
    int d0 = nt*8 + tg*2;
    float o0 = oacc[nt][0]*inv0, o1 = oacc[nt][1]*inv0;
    float o2 = oacc[nt][2]*inv1, o3 = oacc[nt][3]*inv1;
    size_t b0 = ((size_t)(b*NTOK) + n0)*DIM + head*HD + d0;
    size_t b1 = ((size_t)(b*NTOK) + n0 + 8)*DIM + head*HD + d0;
    float h0 = bf16hi(o0), h1 = bf16hi(o1), h2 = bf16hi(o2), h3 = bf16hi(o3);
    *reinterpret_cast<unsigned*>(&g_ah[b0]) = pack2(h0, h1);
    *reinterpret_cast<unsigned*>(&g_al[b0]) = pack2(o0-h0, o1-h1);
    *reinterpret_cast<unsigned*>(&g_ah[b1]) = pack2(h2, h3);
    *reinterpret_cast<unsigned*>(&g_al[b1]) = pack2(o2-h2, o3-h3);
  }
}

extern "C" void kernel_launch(void* const* d_in, const int* in_sizes, int n_in,
                              void* d_out, int out_size) {
  const float* x      = (const float*)d_in[0];
  const float* qkv_w  = (const float*)d_in[1];
  const float* qkv_b  = (const float*)d_in[2];
  const float* proj_w = (const float*)d_in[3];
  const float* proj_b = (const float*)d_in[4];
  const float* rph    = (const float*)d_in[5];
  const float* rpw    = (const float*)d_in[6];
  float* out = (float*)d_out;

  cudaFuncSetAttribute(attn_kernel, cudaFuncAttributeMaxDynamicSharedMemorySize, 72192);

  split_kernel<0><<<(MTOT*DIM + 255)/256, 256>>>(x, MTOT*DIM);
  split_kernel<1><<<(2304*DIM + 255)/256, 256>>>(qkv_w, 2304*DIM);
  split_kernel<2><<<(DIM*DIM + 255)/256, 256>>>(proj_w, DIM*DIM);

  gemm3bf16<0><<<dim3(36, 64), 256>>>(qkv_b, nullptr);
  relpos_kernel<<<dim3(256, 96), 256>>>(rph, rpw);
  attn_kernel<<<dim3(16, 96), 128, 72192>>>();
  gemm3bf16<1><<<dim3(12, 64), 256>>>(proj_b, out);
}

// round 4
// speedup vs baseline: 1.7164x; 1.0203x over previous
#include <cuda_runtime.h>
#include <cuda_bf16.h>

#define HEADS 12
#define NTOK  1024
#define HD    64
#define DIM   768
#define BHT   96
#define MTOT  8192

__device__ __align__(16) __nv_bfloat16 g_xh[MTOT*DIM],  g_xl[MTOT*DIM];
__device__ __align__(16) __nv_bfloat16 g_wh[2304*DIM],  g_wl[2304*DIM];
__device__ __align__(16) __nv_bfloat16 g_pwh[DIM*DIM],  g_pwl[DIM*DIM];
__device__ __align__(16) __nv_bfloat16 g_qh[BHT*NTOK*HD], g_ql[BHT*NTOK*HD];
__device__ __align__(16) __nv_bfloat16 g_kh[BHT*NTOK*HD], g_kl[BHT*NTOK*HD];
__device__ __align__(16) __nv_bfloat16 g_vth[BHT*HD*NTOK], g_vtl[BHT*HD*NTOK]; // V^T (bh,d,n)
__device__ __align__(16) __nv_bfloat16 g_ah[MTOT*DIM],  g_al[MTOT*DIM];
__device__ float g_relh[BHT*NTOK*32];
__device__ float g_relw[BHT*NTOK*32];

__device__ __forceinline__ void mma16816(float* c, const unsigned* a, const unsigned* b) {
  asm volatile(
    "mma.sync.aligned.m16n8k16.row.col.f32.bf16.bf16.f32 "
    "{%0,%1,%2,%3}, {%4,%5,%6,%7}, {%8,%9}, {%0,%1,%2,%3};\n"
    : "+f"(c[0]), "+f"(c[1]), "+f"(c[2]), "+f"(c[3])
    : "r"(a[0]), "r"(a[1]), "r"(a[2]), "r"(a[3]), "r"(b[0]), "r"(b[1]));
}
__device__ __forceinline__ unsigned pack2(float a, float b) {
  __nv_bfloat162 t = __floats2bfloat162_rn(a, b);
  return *reinterpret_cast<unsigned*>(&t);
}
__device__ __forceinline__ float bf16hi(float v) {
  return __bfloat162float(__float2bfloat16(v));
}

template<int W>
__global__ void split_kernel(const float* __restrict__ src, int n) {
  int i = blockIdx.x * 256 + threadIdx.x;
  if (i >= n) return;
  __nv_bfloat16* h = (W==0) ? g_xh : (W==1) ? g_wh : g_pwh;
  __nv_bfloat16* l = (W==0) ? g_xl : (W==1) ? g_wl : g_pwl;
  float v = src[i];
  __nv_bfloat16 hb = __float2bfloat16(v);
  h[i] = hb;
  l[i] = __float2bfloat16(v - __bfloat162float(hb));
}

// C(M,N)=A(M,768)@B(N,768)^T + bias. tile 128x64, 256 thr, warps 4x2.
// EPI0: scatter q/k hi/lo per-head; V written TRANSPOSED (bh,d,n). EPI1: fp32 out.
template<int EPI>
__global__ __launch_bounds__(256, 2) void gemm3bf16(const float* __restrict__ bias,
                                                    float* __restrict__ out) {
  __shared__ unsigned sA_h[128*20], sA_l[128*20], sB_h[64*20], sB_l[64*20];
  const int tid = threadIdx.x, lane = tid & 31, warp = tid >> 5;
  const int wm = warp >> 1, wn = warp & 1;
  const int gr = lane >> 2, tg = lane & 3;
  const int rowA = blockIdx.y * 128, colB = blockIdx.x * 64;

  const unsigned* gAh = reinterpret_cast<const unsigned*>(EPI ? g_ah : g_xh);
  const unsigned* gAl = reinterpret_cast<const unsigned*>(EPI ? g_al : g_xl);
  const unsigned* gBh = reinterpret_cast<const unsigned*>(EPI ? g_pwh : g_wh);
  const unsigned* gBl = reinterpret_cast<const unsigned*>(EPI ? g_pwl : g_wl);

  float acc[2][4][4];
  #pragma unroll
  for (int m = 0; m < 2; m++)
    #pragma unroll
    for (int n = 0; n < 4; n++)
      #pragma unroll
      for (int e = 0; e < 4; e++) acc[m][n][e] = 0.f;

  for (int kt = 0; kt < DIM; kt += 32) {
    __syncthreads();
    #pragma unroll
    for (int i = tid; i < 128*16; i += 256) {
      int r = i >> 4, c = i & 15;
      size_t g = (size_t)(rowA + r) * 384 + (kt >> 1) + c;
      sA_h[r*20 + c] = gAh[g];
      sA_l[r*20 + c] = gAl[g];
    }
    #pragma unroll
    for (int i = tid; i < 64*16; i += 256) {
      int r = i >> 4, c = i & 15;
      size_t g = (size_t)(colB + r) * 384 + (kt >> 1) + c;
      sB_h[r*20 + c] = gBh[g];
      sB_l[r*20 + c] = gBl[g];
    }
    __syncthreads();

    #pragma unroll
    for (int ks = 0; ks < 2; ks++) {
      const int kw = ks * 8;
      unsigned a_h[2][4], a_l[2][4];
      #pragma unroll
      for (int mt = 0; mt < 2; mt++) {
        int r = wm*32 + mt*16 + gr;
        a_h[mt][0] = sA_h[r*20+kw+tg];   a_h[mt][1] = sA_h[(r+8)*20+kw+tg];
        a_h[mt][2] = sA_h[r*20+kw+4+tg]; a_h[mt][3] = sA_h[(r+8)*20+kw+4+tg];
        a_l[mt][0] = sA_l[r*20+kw+tg];   a_l[mt][1] = sA_l[(r+8)*20+kw+tg];
        a_l[mt][2] = sA_l[r*20+kw+4+tg]; a_l[mt][3] = sA_l[(r+8)*20+kw+4+tg];
      }
      #pragma unroll
      for (int nt = 0; nt < 4; nt++) {
        int n = wn*32 + nt*8 + gr;
        unsigned bh[2] = { sB_h[n*20+kw+tg], sB_h[n*20+kw+4+tg] };
        unsigned bl[2] = { sB_l[n*20+kw+tg], sB_l[n*20+kw+4+tg] };
        #pragma unroll
        for (int mt = 0; mt < 2; mt++) {
          mma16816(acc[mt][nt], a_h[mt], bh);
          mma16816(acc[mt][nt], a_h[mt], bl);
          mma16816(acc[mt][nt], a_l[mt], bh);
        }
      }
    }
  }

  if (EPI == 0) {
    const int which = colB / DIM, head = (colB % DIM) / HD;
    #pragma unroll
    for (int mt = 0; mt < 2; mt++) {
      int r = rowA + wm*32 + mt*16 + gr;
      int b = r >> 10, n = r & 1023;
      size_t bhh = (size_t)(b*HEADS + head);
      #pragma unroll
      for (int nt = 0; nt < 4; nt++) {
        int d0 = wn*32 + nt*8 + tg*2;
        float b0 = bias[colB+d0], b1 = bias[colB+d0+1];
        float v0 = acc[mt][nt][0]+b0, v1 = acc[mt][nt][1]+b1;
        float v2 = acc[mt][nt][2]+b0, v3 = acc[mt][nt][3]+b1;
        float h0 = bf16hi(v0), h1 = bf16hi(v1), h2 = bf16hi(v2), h3 = bf16hi(v3);
        if (which == 2) {  // V: transposed store (bh, d, n)
          size_t a0 = (bhh*HD + d0)*NTOK + n, a1 = a0 + NTOK;
          g_vth[a0]   = __float2bfloat16(h0); g_vtl[a0]   = __float2bfloat16(v0-h0);
          g_vth[a1]   = __float2bfloat16(h1); g_vtl[a1]   = __float2bfloat16(v1-h1);
          g_vth[a0+8] = __float2bfloat16(h2); g_vtl[a0+8] = __float2bfloat16(v2-h2);
          g_vth[a1+8] = __float2bfloat16(h3); g_vtl[a1+8] = __float2bfloat16(v3-h3);
        } else {
          __nv_bfloat16* dh = (which==0) ? g_qh : g_kh;
          __nv_bfloat16* dl = (which==0) ? g_ql : g_kl;
          size_t base = (bhh * NTOK + n) * HD;
          *reinterpret_cast<unsigned*>(&dh[base+d0])      = pack2(h0, h1);
          *reinterpret_cast<unsigned*>(&dl[base+d0])      = pack2(v0-h0, v1-h1);
          *reinterpret_cast<unsigned*>(&dh[base+8*HD+d0]) = pack2(h2, h3);
          *reinterpret_cast<unsigned*>(&dl[base+8*HD+d0]) = pack2(v2-h2, v3-h3);
        }
      }
    }
  } else {
    #pragma unroll
    for (int mt = 0; mt < 2; mt++) {
      int r = rowA + wm*32 + mt*16 + gr;
      #pragma unroll
      for (int nt = 0; nt < 4; nt++) {
        int c0 = colB + wn*32 + nt*8 + tg*2;
        float b0 = bias[c0], b1 = bias[c0+1];
        float2 v;
        v.x = acc[mt][nt][0]+b0; v.y = acc[mt][nt][1]+b1;
        *reinterpret_cast<float2*>(&out[(size_t)r*DIM + c0]) = v;
        v.x = acc[mt][nt][2]+b0; v.y = acc[mt][nt][3]+b1;
        *reinterpret_cast<float2*>(&out[(size_t)(r+8)*DIM + c0]) = v;
      }
    }
  }
}

__global__ __launch_bounds__(256) void relpos_kernel(
    const float* __restrict__ rph, const float* __restrict__ rpw) {
  const int bh = blockIdx.y, g = threadIdx.x >> 6, sub = threadIdx.x & 63;
  const int n = blockIdx.x * 4 + g;
  __shared__ float qs[4][64];
  {
    size_t i = ((size_t)bh * NTOK + n) * HD + sub;
    qs[g][sub] = __bfloat162float(g_qh[i]) + __bfloat162float(g_ql[i]);
  }
  __syncthreads();
  const int qh = n >> 5, qw = n & 31;
  const float* tbl; int row; float* o;
  if (sub < 32) {
    row = qh - sub + 31; tbl = rph;
    o = &g_relh[((size_t)bh*NTOK + n)*32 + sub];
  } else {
    int kw = sub - 32;
    row = qw - kw + 31; tbl = rpw;
    o = &g_relw[((size_t)bh*NTOK + n)*32 + kw];
  }
  const float* t = tbl + row*HD;
  float a = 0.f;
  #pragma unroll
  for (int c = 0; c < 64; c++) a += qs[g][c] * t[c];
  *o = a;
}

// fused attention: grid(8,96), 256 thr = 8 warps, warp = 16 q rows (q-tile 128).
// V^T tiles -> direct u32 B-frag loads. no-max softmax. dyn smem 107520B.
__global__ __launch_bounds__(256, 2) void attn_kernel() {
  extern __shared__ unsigned sm[];
  unsigned* sQh = sm;            unsigned* sQl = sQh + 4608;   // 128x36
  unsigned* sKh = sQl + 4608;    unsigned* sKl = sKh + 2304;   // 64x36
  unsigned* sVh = sKl + 2304;    unsigned* sVl = sVh + 2304;   // V^T 64x36
  float* sRh = (float*)(sVl + 2304);                           // 128x33
  float* sRw = sRh + 4224;

  const int bh = blockIdx.y, qt = blockIdx.x, tid = threadIdx.x;
  const int lane = tid & 31, wq = tid >> 5;
  const int gr = lane >> 2, tg = lane & 3;
  const int rq0 = wq*16 + gr;

  {
    const unsigned* gQh = reinterpret_cast<const unsigned*>(g_qh);
    const unsigned* gQl = reinterpret_cast<const unsigned*>(g_ql);
    size_t qb = ((size_t)bh*NTOK + qt*128) * 32;
    #pragma unroll
    for (int i = tid; i < 4096; i += 256) {
      int r = i >> 5, c = i & 31;
      sQh[r*36+c] = gQh[qb+i];
      sQl[r*36+c] = gQl[qb+i];
      sRh[r*33+c] = g_relh[qb+i];
      sRw[r*33+c] = g_relw[qb+i];
    }
  }

  float oacc[8][4];
  #pragma unroll
  for (int n = 0; n < 8; n++)
    #pragma unroll
    for (int e = 0; e < 4; e++) oacc[n][e] = 0.f;
  float rs0 = 0.f, rs1 = 0.f;

  for (int kt = 0; kt < 16; kt++) {
    __syncthreads();
    {
      const unsigned* gKh = reinterpret_cast<const unsigned*>(g_kh);
      const unsigned* gKl = reinterpret_cast<const unsigned*>(g_kl);
      const unsigned* gVh = reinterpret_cast<const unsigned*>(g_vth);
      const unsigned* gVl = reinterpret_cast<const unsigned*>(g_vtl);
      size_t kb = ((size_t)bh*NTOK + kt*64) * 32;
      size_t vb = (size_t)bh*HD*512 + kt*32;
      #pragma unroll
      for (int i = tid; i < 2048; i += 256) {
        int r = i >> 5, c = i & 31;
        sKh[r*36+c] = gKh[kb+i];
        sKl[r*36+c] = gKl[kb+i];
        sVh[r*36+c] = gVh[vb + (size_t)r*512 + c];
        sVl[r*36+c] = gVl[vb + (size_t)r*512 + c];
      }
    }
    __syncthreads();

    float sacc[8][4];
    #pragma unroll
    for (int j = 0; j < 8; j++)
      #pragma unroll
      for (int e = 0; e < 4; e++) sacc[j][e] = 0.f;

    #pragma unroll
    for (int kk = 0; kk < 4; kk++) {
      const int kw = kk * 8;
      unsigned qa_h[4], qa_l[4];
      qa_h[0] = sQh[rq0*36+kw+tg];   qa_h[1] = sQh[(rq0+8)*36+kw+tg];
      qa_h[2] = sQh[rq0*36+kw+4+tg]; qa_h[3] = sQh[(rq0+8)*36+kw+4+tg];
      qa_l[0] = sQl[rq0*36+kw+tg];   qa_l[1] = sQl[(rq0+8)*36+kw+tg];
      qa_l[2] = sQl[rq0*36+kw+4+tg]; qa_l[3] = sQl[(rq0+8)*36+kw+4+tg];
      #pragma unroll
      for (int j = 0; j < 8; j++) {
        int n = j*8 + gr;
        unsigned kb2[2] = { sKh[n*36+kw+tg], sKh[n*36+kw+4+tg] };
        unsigned kl2[2] = { sKl[n*36+kw+tg], sKl[n*36+kw+4+tg] };
        mma16816(sacc[j], qa_h, kb2);
        mma16816(sacc[j], qa_h, kl2);
        mma16816(sacc[j], qa_l, kb2);
      }
    }

    unsigned phi[4][4], plo[4][4];
    #pragma unroll
    for (int j = 0; j < 8; j++) {
      int kh  = kt*2 + (j >> 2);
      int kw0 = (j & 3)*8 + tg*2;
      float rh0 = sRh[rq0*33+kh], rh1 = sRh[(rq0+8)*33+kh];
      float e0 = __expf(fmaf(0.125f, sacc[j][0], rh0 + sRw[rq0*33+kw0]));
      float e1 = __expf(fmaf(0.125f, sacc[j][1], rh0 + sRw[rq0*33+kw0+1]));
      float e2 = __expf(fmaf(0.125f, sacc[j][2], rh1 + sRw[(rq0+8)*33+kw0]));
      float e3 = __expf(fmaf(0.125f, sacc[j][3], rh1 + sRw[(rq0+8)*33+kw0+1]));
      rs0 += e0 + e1;
      rs1 += e2 + e3;
      float h0 = bf16hi(e0), h1 = bf16hi(e1), h2 = bf16hi(e2), h3 = bf16hi(e3);
      phi[j>>1][(j&1)*2]   = pack2(h0, h1);
      phi[j>>1][(j&1)*2+1] = pack2(h2, h3);
      plo[j>>1][(j&1)*2]   = pack2(e0-h0, e1-h1);
      plo[j>>1][(j&1)*2+1] = pack2(e2-h2, e3-h3);
    }

    #pragma unroll
    for (int j16 = 0; j16 < 4; j16++) {
      const int kp = j16*8 + tg;
      #pragma unroll
      for (int nt = 0; nt < 8; nt++) {
        int d = nt*8 + gr;
        unsigned vbh[2] = { sVh[d*36 + kp], sVh[d*36 + kp + 4] };
        unsigned vbl[2] = { sVl[d*36 + kp], sVl[d*36 + kp + 4] };
        mma16816(oacc[nt], phi[j16], vbh);
        mma16816(oacc[nt], phi[j16], vbl);
        mma16816(oacc[nt], plo[j16], vbh);
      }
    }
  }

  rs0 += __shfl_xor_sync(0xffffffffu, rs0, 1);
  rs0 += __shfl_xor_sync(0xffffffffu, rs0, 2);
  rs1 += __shfl_xor_sync(0xffffffffu, rs1, 1);
  rs1 += __shfl_xor_sync(0xffffffffu, rs1, 2);
  const float inv0 = 1.f / rs0, inv1 = 1.f / rs1;

  const int b = bh / HEADS, head = bh % HEADS;
  const int n0 = qt*128 + wq*16 + gr;
  #pragma unroll
  for (int nt = 0; nt < 8; nt++) {
    int d0 = nt*8 + tg*2;
    float o0 = oacc[nt][0]*inv0, o1 = oacc[nt][1]*inv0;
    float o2 = oacc[nt][2]*inv1, o3 = oacc[nt][3]*inv1;
    size_t b0 = ((size_t)(b*NTOK) + n0)*DIM + head*HD + d0;
    size_t b1 = ((size_t)(b*NTOK) + n0 + 8)*DIM + head*HD + d0;
    float h0 = bf16hi(o0), h1 = bf16hi(o1), h2 = bf16hi(o2), h3 = bf16hi(o3);
    *reinterpret_cast<unsigned*>(&g_ah[b0]) = pack2(h0, h1);
    *reinterpret_cast<unsigned*>(&g_al[b0]) = pack2(o0-h0, o1-h1);
    *reinterpret_cast<unsigned*>(&g_ah[b1]) = pack2(h2, h3);
    *reinterpret_cast<unsigned*>(&g_al[b1]) = pack2(o2-h2, o3-h3);
  }
}

extern "C" void kernel_launch(void* const* d_in, const int* in_sizes, int n_in,
                              void* d_out, int out_size) {
  const float* x      = (const float*)d_in[0];
  const float* qkv_w  = (const float*)d_in[1];
  const float* qkv_b  = (const float*)d_in[2];
  const float* proj_w = (const float*)d_in[3];
  const float* proj_b = (const float*)d_in[4];
  const float* rph    = (const float*)d_in[5];
  const float* rpw    = (const float*)d_in[6];
  float* out = (float*)d_out;

  cudaFuncSetAttribute(attn_kernel, cudaFuncAttributeMaxDynamicSharedMemorySize, 107520);

  split_kernel<0><<<(MTOT*DIM + 255)/256, 256>>>(x, MTOT*DIM);
  split_kernel<1><<<(2304*DIM + 255)/256, 256>>>(qkv_w, 2304*DIM);
  split_kernel<2><<<(DIM*DIM + 255)/256, 256>>>(proj_w, DIM*DIM);

  gemm3bf16<0><<<dim3(36, 64), 256>>>(qkv_b, nullptr);
  relpos_kernel<<<dim3(256, 96), 256>>>(rph, rpw);
  attn_kernel<<<dim3(8, 96), 256, 107520>>>();
  gemm3bf16<1><<<dim3(12, 64), 256>>>(proj_b, out);
}

// round 5
// speedup vs baseline: 3.9412x; 2.2962x over previous
#include <cuda_runtime.h>
#include <cuda_bf16.h>

#define HEADS 12
#define NTOK  1024
#define HD    64
#define DIM   768
#define BHT   96
#define MTOT  8192

__device__ __align__(16) __nv_bfloat16 g_xh[MTOT*DIM],  g_xl[MTOT*DIM];
__device__ __align__(16) __nv_bfloat16 g_wh[2304*DIM],  g_wl[2304*DIM];
__device__ __align__(16) __nv_bfloat16 g_pwh[DIM*DIM],  g_pwl[DIM*DIM];
__device__ __align__(16) __nv_bfloat16 g_qh[BHT*NTOK*HD], g_ql[BHT*NTOK*HD];
__device__ __align__(16) __nv_bfloat16 g_kh[BHT*NTOK*HD], g_kl[BHT*NTOK*HD];
__device__ __align__(16) __nv_bfloat16 g_vth[BHT*HD*NTOK], g_vtl[BHT*HD*NTOK]; // V^T (bh,d,n)
__device__ __align__(16) __nv_bfloat16 g_ah[MTOT*DIM],  g_al[MTOT*DIM];
__device__ float g_relh[BHT*NTOK*32];
__device__ float g_relw[BHT*NTOK*32];

__device__ __forceinline__ void mma16816(float* c, const unsigned* a, const unsigned* b) {
  asm volatile(
    "mma.sync.aligned.m16n8k16.row.col.f32.bf16.bf16.f32 "
    "{%0,%1,%2,%3}, {%4,%5,%6,%7}, {%8,%9}, {%0,%1,%2,%3};\n"
    : "+f"(c[0]), "+f"(c[1]), "+f"(c[2]), "+f"(c[3])
    : "r"(a[0]), "r"(a[1]), "r"(a[2]), "r"(a[3]), "r"(b[0]), "r"(b[1]));
}
__device__ __forceinline__ unsigned pack2(float a, float b) {
  __nv_bfloat162 t = __floats2bfloat162_rn(a, b);
  return *reinterpret_cast<unsigned*>(&t);
}
__device__ __forceinline__ float bf16hi(float v) {
  return __bfloat162float(__float2bfloat16(v));
}

template<int W>
__global__ void split_kernel(const float* __restrict__ src, int n) {
  int i = blockIdx.x * 256 + threadIdx.x;
  if (i >= n) return;
  __nv_bfloat16* h = (W==0) ? g_xh : (W==1) ? g_wh : g_pwh;
  __nv_bfloat16* l = (W==0) ? g_xl : (W==1) ? g_wl : g_pwl;
  float v = src[i];
  __nv_bfloat16 hb = __float2bfloat16(v);
  h[i] = hb;
  l[i] = __float2bfloat16(v - __bfloat162float(hb));
}

// C(M,N)=A(M,768)@B(N,768)^T + bias. tile 128x64, 256 thr, warps 4x2.
template<int EPI>
__global__ __launch_bounds__(256, 2) void gemm3bf16(const float* __restrict__ bias,
                                                    float* __restrict__ out) {
  __shared__ unsigned sA_h[128*20], sA_l[128*20], sB_h[64*20], sB_l[64*20];
  const int tid = threadIdx.x, lane = tid & 31, warp = tid >> 5;
  const int wm = warp >> 1, wn = warp & 1;
  const int gr = lane >> 2, tg = lane & 3;
  const int rowA = blockIdx.y * 128, colB = blockIdx.x * 64;

  const unsigned* gAh = reinterpret_cast<const unsigned*>(EPI ? g_ah : g_xh);
  const unsigned* gAl = reinterpret_cast<const unsigned*>(EPI ? g_al : g_xl);
  const unsigned* gBh = reinterpret_cast<const unsigned*>(EPI ? g_pwh : g_wh);
  const unsigned* gBl = reinterpret_cast<const unsigned*>(EPI ? g_pwl : g_wl);

  float acc[2][4][4];
  #pragma unroll
  for (int m = 0; m < 2; m++)
    #pragma unroll
    for (int n = 0; n < 4; n++)
      #pragma unroll
      for (int e = 0; e < 4; e++) acc[m][n][e] = 0.f;

  for (int kt = 0; kt < DIM; kt += 32) {
    __syncthreads();
    #pragma unroll
    for (int i = tid; i < 128*16; i += 256) {
      int r = i >> 4, c = i & 15;
      size_t g = (size_t)(rowA + r) * 384 + (kt >> 1) + c;
      sA_h[r*20 + c] = gAh[g];
      sA_l[r*20 + c] = gAl[g];
    }
    #pragma unroll
    for (int i = tid; i < 64*16; i += 256) {
      int r = i >> 4, c = i & 15;
      size_t g = (size_t)(colB + r) * 384 + (kt >> 1) + c;
      sB_h[r*20 + c] = gBh[g];
      sB_l[r*20 + c] = gBl[g];
    }
    __syncthreads();

    #pragma unroll
    for (int ks = 0; ks < 2; ks++) {
      const int kw = ks * 8;
      unsigned a_h[2][4], a_l[2][4];
      #pragma unroll
      for (int mt = 0; mt < 2; mt++) {
        int r = wm*32 + mt*16 + gr;
        a_h[mt][0] = sA_h[r*20+kw+tg];   a_h[mt][1] = sA_h[(r+8)*20+kw+tg];
        a_h[mt][2] = sA_h[r*20+kw+4+tg]; a_h[mt][3] = sA_h[(r+8)*20+kw+4+tg];
        a_l[mt][0] = sA_l[r*20+kw+tg];   a_l[mt][1] = sA_l[(r+8)*20+kw+tg];
        a_l[mt][2] = sA_l[r*20+kw+4+tg]; a_l[mt][3] = sA_l[(r+8)*20+kw+4+tg];
      }
      #pragma unroll
      for (int nt = 0; nt < 4; nt++) {
        int n = wn*32 + nt*8 + gr;
        unsigned bh[2] = { sB_h[n*20+kw+tg], sB_h[n*20+kw+4+tg] };
        unsigned bl[2] = { sB_l[n*20+kw+tg], sB_l[n*20+kw+4+tg] };
        #pragma unroll
        for (int mt = 0; mt < 2; mt++) {
          mma16816(acc[mt][nt], a_h[mt], bh);
          mma16816(acc[mt][nt], a_h[mt], bl);
          mma16816(acc[mt][nt], a_l[mt], bh);
        }
      }
    }
  }

  if (EPI == 0) {
    const int which = colB / DIM, head = (colB % DIM) / HD;
    #pragma unroll
    for (int mt = 0; mt < 2; mt++) {
      int r = rowA + wm*32 + mt*16 + gr;
      int b = r >> 10, n = r & 1023;
      size_t bhh = (size_t)(b*HEADS + head);
      #pragma unroll
      for (int nt = 0; nt < 4; nt++) {
        int d0 = wn*32 + nt*8 + tg*2;
        float b0 = bias[colB+d0], b1 = bias[colB+d0+1];
        float v0 = acc[mt][nt][0]+b0, v1 = acc[mt][nt][1]+b1;
        float v2 = acc[mt][nt][2]+b0, v3 = acc[mt][nt][3]+b1;
        float h0 = bf16hi(v0), h1 = bf16hi(v1), h2 = bf16hi(v2), h3 = bf16hi(v3);
        if (which == 2) {
          size_t a0 = (bhh*HD + d0)*NTOK + n, a1 = a0 + NTOK;
          g_vth[a0]   = __float2bfloat16(h0); g_vtl[a0]   = __float2bfloat16(v0-h0);
          g_vth[a1]   = __float2bfloat16(h1); g_vtl[a1]   = __float2bfloat16(v1-h1);
          g_vth[a0+8] = __float2bfloat16(h2); g_vtl[a0+8] = __float2bfloat16(v2-h2);
          g_vth[a1+8] = __float2bfloat16(h3); g_vtl[a1+8] = __float2bfloat16(v3-h3);
        } else {
          __nv_bfloat16* dh = (which==0) ? g_qh : g_kh;
          __nv_bfloat16* dl = (which==0) ? g_ql : g_kl;
          size_t base = (bhh * NTOK + n) * HD;
          *reinterpret_cast<unsigned*>(&dh[base+d0])      = pack2(h0, h1);
          *reinterpret_cast<unsigned*>(&dl[base+d0])      = pack2(v0-h0, v1-h1);
          *reinterpret_cast<unsigned*>(&dh[base+8*HD+d0]) = pack2(h2, h3);
          *reinterpret_cast<unsigned*>(&dl[base+8*HD+d0]) = pack2(v2-h2, v3-h3);
        }
      }
    }
  } else {
    #pragma unroll
    for (int mt = 0; mt < 2; mt++) {
      int r = rowA + wm*32 + mt*16 + gr;
      #pragma unroll
      for (int nt = 0; nt < 4; nt++) {
        int c0 = colB + wn*32 + nt*8 + tg*2;
        float b0 = bias[c0], b1 = bias[c0+1];
        float2 v;
        v.x = acc[mt][nt][0]+b0; v.y = acc[mt][nt][1]+b1;
        *reinterpret_cast<float2*>(&out[(size_t)r*DIM + c0]) = v;
        v.x = acc[mt][nt][2]+b0; v.y = acc[mt][nt][3]+b1;
        *reinterpret_cast<float2*>(&out[(size_t)(r+8)*DIM + c0]) = v;
      }
    }
  }
}

// rel-pos: smem-cached tables. grid(16,96), 256 thr, 64 tokens/block.
// dyn smem: sq 64*64 + sH 63*65 + sW 63*65 floats = 49144 B.
__global__ __launch_bounds__(256) void relpos_kernel(
    const float* __restrict__ rph, const float* __restrict__ rpw) {
  extern __shared__ float rsm[];
  float* sq = rsm;             // [64][64]
  float* sH = sq + 64*64;      // [63][65] padded
  float* sW = sH + 63*65;      // [63][65]

  const int bh = blockIdx.y;
  const int n0 = blockIdx.x * 64;
  const int tid = threadIdx.x;

  for (int i = tid; i < 63*64; i += 256) {
    int r = i >> 6, c = i & 63;
    sH[r*65 + c] = rph[i];
    sW[r*65 + c] = rpw[i];
  }
  {
    size_t base = ((size_t)bh * NTOK + n0) * HD;
    for (int i = tid; i < 64*64; i += 256)
      sq[i] = __bfloat162float(g_qh[base + i]) + __bfloat162float(g_ql[base + i]);
  }
  __syncthreads();

  const int tok  = tid >> 2;          // 0..63
  const int part = tid & 3;           // 0..3
  const int n  = n0 + tok;
  const int qh = n >> 5, qw = n & 31;
  const float* qrow = sq + tok * 64;

  #pragma unroll
  for (int i = 0; i < 16; i++) {
    const int idx = part * 16 + i;    // 0..63
    const float* trow;
    float* o;
    if (idx < 32) {
      trow = sH + (qh - idx + 31) * 65;
      o = &g_relh[((size_t)bh*NTOK + n)*32 + idx];
    } else {
      const int kw = idx - 32;
      trow = sW + (qw - kw + 31) * 65;
      o = &g_relw[((size_t)bh*NTOK + n)*32 + kw];
    }
    float a = 0.f;
    #pragma unroll
    for (int c = 0; c < 64; c++) a += qrow[c] * trow[c];
    *o = a;
  }
}

// fused attention: grid(8,96), 256 thr = 8 warps, warp = 16 q rows.
__global__ __launch_bounds__(256, 2) void attn_kernel() {
  extern __shared__ unsigned sm[];
  unsigned* sQh = sm;            unsigned* sQl = sQh + 4608;   // 128x36
  unsigned* sKh = sQl + 4608;    unsigned* sKl = sKh + 2304;   // 64x36
  unsigned* sVh = sKl + 2304;    unsigned* sVl = sVh + 2304;   // V^T 64x36
  float* sRh = (float*)(sVl + 2304);                           // 128x33
  float* sRw = sRh + 4224;

  const int bh = blockIdx.y, qt = blockIdx.x, tid = threadIdx.x;
  const int lane = tid & 31, wq = tid >> 5;
  const int gr = lane >> 2, tg = lane & 3;
  const int rq0 = wq*16 + gr;

  {
    const unsigned* gQh = reinterpret_cast<const unsigned*>(g_qh);
    const unsigned* gQl = reinterpret_cast<const unsigned*>(g_ql);
    size_t qb = ((size_t)bh*NTOK + qt*128) * 32;
    #pragma unroll
    for (int i = tid; i < 4096; i += 256) {
      int r = i >> 5, c = i & 31;
      sQh[r*36+c] = gQh[qb+i];
      sQl[r*36+c] = gQl[qb+i];
      sRh[r*33+c] = g_relh[qb+i];
      sRw[r*33+c] = g_relw[qb+i];
    }
  }

  float oacc[8][4];
  #pragma unroll
  for (int n = 0; n < 8; n++)
    #pragma unroll
    for (int e = 0; e < 4; e++) oacc[n][e] = 0.f;
  float rs0 = 0.f, rs1 = 0.f;

  for (int kt = 0; kt < 16; kt++) {
    __syncthreads();
    {
      const unsigned* gKh = reinterpret_cast<const unsigned*>(g_kh);
      const unsigned* gKl = reinterpret_cast<const unsigned*>(g_kl);
      const unsigned* gVh = reinterpret_cast<const unsigned*>(g_vth);
      const unsigned* gVl = reinterpret_cast<const unsigned*>(g_vtl);
      size_t kb = ((size_t)bh*NTOK + kt*64) * 32;
      size_t vb = (size_t)bh*HD*512 + kt*32;
      #pragma unroll
      for (int i = tid; i < 2048; i += 256) {
        int r = i >> 5, c = i & 31;
        sKh[r*36+c] = gKh[kb+i];
        sKl[r*36+c] = gKl[kb+i];
        sVh[r*36+c] = gVh[vb + (size_t)r*512 + c];
        sVl[r*36+c] = gVl[vb + (size_t)r*512 + c];
      }
    }
    __syncthreads();

    float sacc[8][4];
    #pragma unroll
    for (int j = 0; j < 8; j++)
      #pragma unroll
      for (int e = 0; e < 4; e++) sacc[j][e] = 0.f;

    #pragma unroll
    for (int kk = 0; kk < 4; kk++) {
      const int kw = kk * 8;
      unsigned qa_h[4], qa_l[4];
      qa_h[0] = sQh[rq0*36+kw+tg];   qa_h[1] = sQh[(rq0+8)*36+kw+tg];
      qa_h[2] = sQh[rq0*36+kw+4+tg]; qa_h[3] = sQh[(rq0+8)*36+kw+4+tg];
      qa_l[0] = sQl[rq0*36+kw+tg];   qa_l[1] = sQl[(rq0+8)*36+kw+tg];
      qa_l[2] = sQl[rq0*36+kw+4+tg]; qa_l[3] = sQl[(rq0+8)*36+kw+4+tg];
      #pragma unroll
      for (int j = 0; j < 8; j++) {
        int n = j*8 + gr;
        unsigned kb2[2] = { sKh[n*36+kw+tg], sKh[n*36+kw+4+tg] };
        unsigned kl2[2] = { sKl[n*36+kw+tg], sKl[n*36+kw+4+tg] };
        mma16816(sacc[j], qa_h, kb2);
        mma16816(sacc[j], qa_h, kl2);
        mma16816(sacc[j], qa_l, kb2);
      }
    }

    unsigned phi[4][4], plo[4][4];
    #pragma unroll
    for (int j = 0; j < 8; j++) {
      int kh  = kt*2 + (j >> 2);
      int kw0 = (j & 3)*8 + tg*2;
      float rh0 = sRh[rq0*33+kh], rh1 = sRh[(rq0+8)*33+kh];
      float e0 = __expf(fmaf(0.125f, sacc[j][0], rh0 + sRw[rq0*33+kw0]));
      float e1 = __expf(fmaf(0.125f, sacc[j][1], rh0 + sRw[rq0*33+kw0+1]));
      float e2 = __expf(fmaf(0.125f, sacc[j][2], rh1 + sRw[(rq0+8)*33+kw0]));
      float e3 = __expf(fmaf(0.125f, sacc[j][3], rh1 + sRw[(rq0+8)*33+kw0+1]));
      rs0 += e0 + e1;
      rs1 += e2 + e3;
      float h0 = bf16hi(e0), h1 = bf16hi(e1), h2 = bf16hi(e2), h3 = bf16hi(e3);
      phi[j>>1][(j&1)*2]   = pack2(h0, h1);
      phi[j>>1][(j&1)*2+1] = pack2(h2, h3);
      plo[j>>1][(j&1)*2]   = pack2(e0-h0, e1-h1);
      plo[j>>1][(j&1)*2+1] = pack2(e2-h2, e3-h3);
    }

    #pragma unroll
    for (int j16 = 0; j16 < 4; j16++) {
      const int kp = j16*8 + tg;
      #pragma unroll
      for (int nt = 0; nt < 8; nt++) {
        int d = nt*8 + gr;
        unsigned vbh[2] = { sVh[d*36 + kp], sVh[d*36 + kp + 4] };
        unsigned vbl[2] = { sVl[d*36 + kp], sVl[d*36 + kp + 4] };
        mma16816(oacc[nt], phi[j16], vbh);
        mma16816(oacc[nt], phi[j16], vbl);
        mma16816(oacc[nt], plo[j16], vbh);
      }
    }
  }

  rs0 += __shfl_xor_sync(0xffffffffu, rs0, 1);
  rs0 += __shfl_xor_sync(0xffffffffu, rs0, 2);
  rs1 += __shfl_xor_sync(0xffffffffu, rs1, 1);
  rs1 += __shfl_xor_sync(0xffffffffu, rs1, 2);
  const float inv0 = 1.f / rs0, inv1 = 1.f / rs1;

  const int b = bh / HEADS, head = bh % HEADS;
  const int n0 = qt*128 + wq*16 + gr;
  #pragma unroll
  for (int nt = 0; nt < 8; nt++) {
    int d0 = nt*8 + tg*2;
    float o0 = oacc[nt][0]*inv0, o1 = oacc[nt][1]*inv0;
    float o2 = oacc[nt][2]*inv1, o3 = oacc[nt][3]*inv1;
    size_t b0 = ((size_t)(b*NTOK) + n0)*DIM + head*HD + d0;
    size_t b1 = ((size_t)(b*NTOK) + n0 + 8)*DIM + head*HD + d0;
    float h0 = bf16hi(o0), h1 = bf16hi(o1), h2 = bf16hi(o2), h3 = bf16hi(o3);
    *reinterpret_cast<unsigned*>(&g_ah[b0]) = pack2(h0, h1);
    *reinterpret_cast<unsigned*>(&g_al[b0]) = pack2(o0-h0, o1-h1);
    *reinterpret_cast<unsigned*>(&g_ah[b1]) = pack2(h2, h3);
    *reinterpret_cast<unsigned*>(&g_al[b1]) = pack2(o2-h2, o3-h3);
  }
}

extern "C" void kernel_launch(void* const* d_in, const int* in_sizes, int n_in,
                              void* d_out, int out_size) {
  const float* x      = (const float*)d_in[0];
  const float* qkv_w  = (const float*)d_in[1];
  const float* qkv_b  = (const float*)d_in[2];
  const float* proj_w = (const float*)d_in[3];
  const float* proj_b = (const float*)d_in[4];
  const float* rph    = (const float*)d_in[5];
  const float* rpw    = (const float*)d_in[6];
  float* out = (float*)d_out;

  cudaFuncSetAttribute(attn_kernel, cudaFuncAttributeMaxDynamicSharedMemorySize, 107520);
  cudaFuncSetAttribute(relpos_kernel, cudaFuncAttributeMaxDynamicSharedMemorySize, 49152);

  split_kernel<0><<<(MTOT*DIM + 255)/256, 256>>>(x, MTOT*DIM);
  split_kernel<1><<<(2304*DIM + 255)/256, 256>>>(qkv_w, 2304*DIM);
  split_kernel<2><<<(DIM*DIM + 255)/256, 256>>>(proj_w, DIM*DIM);

  gemm3bf16<0><<<dim3(36, 64), 256>>>(qkv_b, nullptr);
  relpos_kernel<<<dim3(16, 96), 256, 49152>>>(rph, rpw);
  attn_kernel<<<dim3(8, 96), 256, 107520>>>();
  gemm3bf16<1><<<dim3(12, 64), 256>>>(proj_b, out);
}

// round 8
// speedup vs baseline: 4.4591x; 1.1314x over previous
#include <cuda_runtime.h>
#include <cuda_bf16.h>
#include <cstdint>

#define HEADS 12
#define NTOK  1024
#define HD    64
#define DIM   768
#define BHT   96
#define MTOT  8192

__device__ __align__(16) __nv_bfloat16 g_xh[MTOT*DIM],  g_xl[MTOT*DIM];
__device__ __align__(16) __nv_bfloat16 g_wh[2304*DIM],  g_wl[2304*DIM];
__device__ __align__(16) __nv_bfloat16 g_pwh[DIM*DIM],  g_pwl[DIM*DIM];
__device__ __align__(16) __nv_bfloat16 g_qh[BHT*NTOK*HD], g_ql[BHT*NTOK*HD];
__device__ __align__(16) __nv_bfloat16 g_kh[BHT*NTOK*HD], g_kl[BHT*NTOK*HD];
__device__ __align__(16) __nv_bfloat16 g_vth[BHT*HD*NTOK], g_vtl[BHT*HD*NTOK];
__device__ __align__(16) __nv_bfloat16 g_ah[MTOT*DIM],  g_al[MTOT*DIM];
__device__ float g_relh[BHT*NTOK*32];
__device__ float g_relw[BHT*NTOK*32];

__device__ __forceinline__ void mma16816(float* c, const unsigned* a, const unsigned* b) {
  asm volatile(
    "mma.sync.aligned.m16n8k16.row.col.f32.bf16.bf16.f32 "
    "{%0,%1,%2,%3}, {%4,%5,%6,%7}, {%8,%9}, {%0,%1,%2,%3};\n"
    : "+f"(c[0]), "+f"(c[1]), "+f"(c[2]), "+f"(c[3])
    : "r"(a[0]), "r"(a[1]), "r"(a[2]), "r"(a[3]), "r"(b[0]), "r"(b[1]));
}
__device__ __forceinline__ unsigned pack2(float a, float b) {
  __nv_bfloat162 t = __floats2bfloat162_rn(a, b);
  return *reinterpret_cast<unsigned*>(&t);
}
__device__ __forceinline__ float bf16hi(float v) {
  return __bfloat162float(__float2bfloat16(v));
}
__device__ __forceinline__ uint32_t s2u(const void* p) {
  uint32_t a;
  asm("{ .reg .u64 t; cvta.to.shared.u64 t, %1; cvt.u32.u64 %0, t; }" : "=r"(a) : "l"(p));
  return a;
}
#define LDSM4(r, a) \
  asm volatile("ldmatrix.sync.aligned.m8n8.x4.shared.b16 {%0,%1,%2,%3},[%4];" \
    : "=r"((r)[0]), "=r"((r)[1]), "=r"((r)[2]), "=r"((r)[3]) : "r"(a))
#define CP16(s, g) \
  asm volatile("cp.async.cg.shared.global [%0],[%1],16;" :: "r"(s), "l"(g))
#define CP_COMMIT asm volatile("cp.async.commit_group;" ::: "memory")
#define CP_WAIT1  asm volatile("cp.async.wait_group 1;" ::: "memory")
#define CP_WAIT0  asm volatile("cp.async.wait_group 0;" ::: "memory")

template<int W>
__global__ void split_kernel(const float* __restrict__ src, int n) {
  int i = blockIdx.x * 256 + threadIdx.x;
  if (i >= n) return;
  __nv_bfloat16* h = (W==0) ? g_xh : (W==1) ? g_wh : g_pwh;
  __nv_bfloat16* l = (W==0) ? g_xl : (W==1) ? g_wl : g_pwl;
  float v = src[i];
  __nv_bfloat16 hb = __float2bfloat16(v);
  h[i] = hb;
  l[i] = __float2bfloat16(v - __bfloat162float(hb));
}

// GEMM: C(M,N)=A(M,768)@B(N,768)^T + bias. tile 128x64, warps 4x2.
// cp.async double-buffered, 24 K-chunks of 32 bf16 (16 u32), ldmatrix frags.
// buf (u32): Ah[2560] Al[2560] Bh[1280] Bl[1280] = 30720B, x2 bufs.
template<int EPI>
__global__ __launch_bounds__(256, 2) void gemm3bf16(const float* __restrict__ bias,
                                                    float* __restrict__ out) {
  extern __shared__ __align__(16) unsigned dynsm[];
  const int tid = threadIdx.x, lane = tid & 31, warp = tid >> 5;
  const int wm = warp >> 1, wn = warp & 1;
  const int gr = lane >> 2, tg = lane & 3;
  const int rowA = blockIdx.y * 128, colB = blockIdx.x * 64;

  const unsigned* gAh = (const unsigned*)(EPI ? g_ah : g_xh);
  const unsigned* gAl = (const unsigned*)(EPI ? g_al : g_xl);
  const unsigned* gBh = (const unsigned*)(EPI ? g_pwh : g_wh);
  const unsigned* gBl = (const unsigned*)(EPI ? g_pwl : g_wl);

  const uint32_t sb0 = s2u(dynsm);
  // per-lane ldmatrix offsets (bytes), row stride 80B
  const uint32_t aoff = ((wm*32 + (lane&7) + ((lane>>3)&1)*8)*20 + (lane>>4)*4)*4;
  const uint32_t boff = ((wn*32 + (lane&7) + (lane>>4)*8)*20 + ((lane>>3)&1)*4)*4;

  const int ar = tid >> 2, aq = (tid & 3) * 4;   // staging coords

  auto stage = [&](int c, int b) {
    uint32_t sb = sb0 + b*30720;
    uint32_t off = (ar*20 + aq)*4;
    CP16(sb + off,          gAh + (size_t)(rowA + ar)*384 + c*16 + aq);
    CP16(sb + 10240 + off,  gAl + (size_t)(rowA + ar)*384 + c*16 + aq);
    CP16(sb + off + 64*80,          gAh + (size_t)(rowA + 64 + ar)*384 + c*16 + aq);
    CP16(sb + 10240 + off + 64*80,  gAl + (size_t)(rowA + 64 + ar)*384 + c*16 + aq);
    CP16(sb + 20480 + off,  gBh + (size_t)(colB + ar)*384 + c*16 + aq);
    CP16(sb + 25600 + off,  gBl + (size_t)(colB + ar)*384 + c*16 + aq);
  };

  float acc[2][4][4];
  #pragma unroll
  for (int m = 0; m < 2; m++)
    #pragma unroll
    for (int n = 0; n < 4; n++)
      #pragma unroll
      for (int e = 0; e < 4; e++) acc[m][n][e] = 0.f;

  stage(0, 0); CP_COMMIT;
  for (int c = 0; c < 24; c++) {
    if (c < 23) { stage(c+1, (c+1)&1); CP_COMMIT; CP_WAIT1; }
    else        { CP_WAIT0; }
    __syncthreads();
    const uint32_t sb = sb0 + (c&1)*30720;
    #pragma unroll
    for (int ks = 0; ks < 2; ks++) {
      unsigned ah[2][4], al[2][4];
      LDSM4(ah[0], sb + aoff + ks*32);
      LDSM4(ah[1], sb + aoff + 1280 + ks*32);
      LDSM4(al[0], sb + 10240 + aoff + ks*32);
      LDSM4(al[1], sb + 10240 + aoff + 1280 + ks*32);
      #pragma unroll
      for (int p = 0; p < 2; p++) {
        unsigned bh4[4], bl4[4];
        LDSM4(bh4, sb + 20480 + boff + p*1280 + ks*32);
        LDSM4(bl4, sb + 25600 + boff + p*1280 + ks*32);
        #pragma unroll
        for (int h = 0; h < 2; h++) {
          const int nt = 2*p + h;
          unsigned bh2[2] = { bh4[2*h], bh4[2*h+1] };
          unsigned bl2[2] = { bl4[2*h], bl4[2*h+1] };
          #pragma unroll
          for (int mt = 0; mt < 2; mt++) {
            mma16816(acc[mt][nt], ah[mt], bh2);
            mma16816(acc[mt][nt], ah[mt], bl2);
            mma16816(acc[mt][nt], al[mt], bh2);
          }
        }
      }
    }
    __syncthreads();
  }

  if (EPI == 0) {
    const int which = colB / DIM, head = (colB % DIM) / HD;
    #pragma unroll
    for (int mt = 0; mt < 2; mt++) {
      int r = rowA + wm*32 + mt*16 + gr;
      int b = r >> 10, n = r & 1023;
      size_t bhh = (size_t)(b*HEADS + head);
      #pragma unroll
      for (int nt = 0; nt < 4; nt++) {
        int d0 = wn*32 + nt*8 + tg*2;
        float b0 = bias[colB+d0], b1 = bias[colB+d0+1];
        float v0 = acc[mt][nt][0]+b0, v1 = acc[mt][nt][1]+b1;
        float v2 = acc[mt][nt][2]+b0, v3 = acc[mt][nt][3]+b1;
        float h0 = bf16hi(v0), h1 = bf16hi(v1), h2 = bf16hi(v2), h3 = bf16hi(v3);
        if (which == 2) {
          size_t a0 = (bhh*HD + d0)*NTOK + n, a1 = a0 + NTOK;
          g_vth[a0]   = __float2bfloat16(h0); g_vtl[a0]   = __float2bfloat16(v0-h0);
          g_vth[a1]   = __float2bfloat16(h1); g_vtl[a1]   = __float2bfloat16(v1-h1);
          g_vth[a0+8] = __float2bfloat16(h2); g_vtl[a0+8] = __float2bfloat16(v2-h2);
          g_vth[a1+8] = __float2bfloat16(h3); g_vtl[a1+8] = __float2bfloat16(v3-h3);
        } else {
          __nv_bfloat16* dh = which ? g_kh : g_qh;
          __nv_bfloat16* dl = which ? g_kl : g_ql;
          size_t base = (bhh * NTOK + n) * HD;
          *(unsigned*)&dh[base+d0]      = pack2(h0, h1);
          *(unsigned*)&dl[base+d0]      = pack2(v0-h0, v1-h1);
          *(unsigned*)&dh[base+8*HD+d0] = pack2(h2, h3);
          *(unsigned*)&dl[base+8*HD+d0] = pack2(v2-h2, v3-h3);
        }
      }
    }
  } else {
    #pragma unroll
    for (int mt = 0; mt < 2; mt++) {
      int r = rowA + wm*32 + mt*16 + gr;
      #pragma unroll
      for (int nt = 0; nt < 4; nt++) {
        int c0 = colB + wn*32 + nt*8 + tg*2;
        float b0 = bias[c0], b1 = bias[c0+1];
        float2 v;
        v.x = acc[mt][nt][0]+b0; v.y = acc[mt][nt][1]+b1;
        *(float2*)&out[(size_t)r*DIM + c0] = v;
        v.x = acc[mt][nt][2]+b0; v.y = acc[mt][nt][3]+b1;
        *(float2*)&out[(size_t)(r+8)*DIM + c0] = v;
      }
    }
  }
}

// rel-pos: smem-cached tables. grid(16,96), 256 thr.
__global__ __launch_bounds__(256) void relpos_kernel(
    const float* __restrict__ rph, const float* __restrict__ rpw) {
  extern __shared__ float rsm[];
  float* sq = rsm;
  float* sH = sq + 64*64;
  float* sW = sH + 63*65;
  const int bh = blockIdx.y, n0 = blockIdx.x * 64, tid = threadIdx.x;
  for (int i = tid; i < 63*64; i += 256) {
    int r = i >> 6, c = i & 63;
    sH[r*65 + c] = rph[i];
    sW[r*65 + c] = rpw[i];
  }
  {
    size_t base = ((size_t)bh * NTOK + n0) * HD;
    for (int i = tid; i < 64*64; i += 256)
      sq[i] = __bfloat162float(g_qh[base + i]) + __bfloat162float(g_ql[base + i]);
  }
  __syncthreads();
  const int tok = tid >> 2, part = tid & 3;
  const int n = n0 + tok, qh = n >> 5, qw = n & 31;
  const float* qrow = sq + tok * 64;
  #pragma unroll
  for (int i = 0; i < 16; i++) {
    const int idx = part * 16 + i;
    const float* trow; float* o;
    if (idx < 32) {
      trow = sH + (qh - idx + 31) * 65;
      o = &g_relh[((size_t)bh*NTOK + n)*32 + idx];
    } else {
      const int kw = idx - 32;
      trow = sW + (qw - kw + 31) * 65;
      o = &g_relw[((size_t)bh*NTOK + n)*32 + kw];
    }
    float a = 0.f;
    #pragma unroll
    for (int c = 0; c < 64; c++) a += qrow[c] * trow[c];
    *o = a;
  }
}

// fused attention: grid(8,96), 256 thr = 8 warps, warp = 16 q rows. ldmatrix frags.
__global__ __launch_bounds__(256, 2) void attn_kernel() {
  extern __shared__ unsigned sm[];
  unsigned* sQh = sm;            unsigned* sQl = sQh + 4608;   // 128x36
  unsigned* sKh = sQl + 4608;    unsigned* sKl = sKh + 2304;   // 64x36
  unsigned* sVh = sKl + 2304;    unsigned* sVl = sVh + 2304;   // V^T 64x36
  float* sRh = (float*)(sVl + 2304);                           // 128x33
  float* sRw = sRh + 4224;

  const int bh = blockIdx.y, qt = blockIdx.x, tid = threadIdx.x;
  const int lane = tid & 31, wq = tid >> 5;
  const int gr = lane >> 2, tg = lane & 3;
  const int rq0 = wq*16 + gr;

  // ldmatrix per-lane offsets (bytes), row stride 144B
  const uint32_t aoffQ = ((wq*16 + (lane&7) + ((lane>>3)&1)*8)*36 + (lane>>4)*4)*4;
  const uint32_t boffB = (((lane&7) + (lane>>4)*8)*36 + ((lane>>3)&1)*4)*4;
  const uint32_t uQh = s2u(sQh), uKh = s2u(sKh), uVh = s2u(sVh);

  {
    const unsigned* gQh = (const unsigned*)g_qh;
    const unsigned* gQl = (const unsigned*)g_ql;
    size_t qb = ((size_t)bh*NTOK + qt*128) * 32;
    #pragma unroll
    for (int i = tid; i < 4096; i += 256) {
      int r = i >> 5, c = i & 31;
      sQh[r*36+c] = gQh[qb+i];
      sQl[r*36+c] = gQl[qb+i];
      sRh[r*33+c] = g_relh[qb+i];
      sRw[r*33+c] = g_relw[qb+i];
    }
  }

  float oacc[8][4];
  #pragma unroll
  for (int n = 0; n < 8; n++)
    #pragma unroll
    for (int e = 0; e < 4; e++) oacc[n][e] = 0.f;
  float rs0 = 0.f, rs1 = 0.f;

  for (int kt = 0; kt < 16; kt++) {
    __syncthreads();
    {
      const unsigned* gKh = (const unsigned*)g_kh;
      const unsigned* gKl = (const unsigned*)g_kl;
      const unsigned* gVh = (const unsigned*)g_vth;
      const unsigned* gVl = (const unsigned*)g_vtl;
      size_t kb = ((size_t)bh*NTOK + kt*64) * 32;
      size_t vb = (size_t)bh*HD*512 + kt*32;
      #pragma unroll
      for (int i = tid; i < 2048; i += 256) {
        int r = i >> 5, c = i & 31;
        sKh[r*36+c] = gKh[kb+i];
        sKl[r*36+c] = gKl[kb+i];
        sVh[r*36+c] = gVh[vb + (size_t)r*512 + c];
        sVl[r*36+c] = gVl[vb + (size_t)r*512 + c];
      }
    }
    __syncthreads();

    float sacc[8][4];
    #pragma unroll
    for (int j = 0; j < 8; j++)
      #pragma unroll
      for (int e = 0; e < 4; e++) sacc[j][e] = 0.f;

    #pragma unroll
    for (int kk = 0; kk < 4; kk++) {
      unsigned qa_h[4], qa_l[4];
      LDSM4(qa_h, uQh + aoffQ + kk*32);
      LDSM4(qa_l, uQh + 18432 + aoffQ + kk*32);
      #pragma unroll
      for (int p = 0; p < 4; p++) {
        unsigned kh4[4], kl4[4];
        LDSM4(kh4, uKh + boffB + p*2304 + kk*32);
        LDSM4(kl4, uKh + 9216 + boffB + p*2304 + kk*32);
        #pragma unroll
        for (int h = 0; h < 2; h++) {
          const int j = 2*p + h;
          unsigned b2[2] = { kh4[2*h], kh4[2*h+1] };
          unsigned l2[2] = { kl4[2*h], kl4[2*h+1] };
          mma16816(sacc[j], qa_h, b2);
          mma16816(sacc[j], qa_h, l2);
          mma16816(sacc[j], qa_l, b2);
        }
      }
    }

    unsigned phi[4][4], plo[4][4];
    #pragma unroll
    for (int j = 0; j < 8; j++) {
      int kh  = kt*2 + (j >> 2);
      int kw0 = (j & 3)*8 + tg*2;
      float rh0 = sRh[rq0*33+kh], rh1 = sRh[(rq0+8)*33+kh];
      float e0 = __expf(fmaf(0.125f, sacc[j][0], rh0 + sRw[rq0*33+kw0]));
      float e1 = __expf(fmaf(0.125f, sacc[j][1], rh0 + sRw[rq0*33+kw0+1]));
      float e2 = __expf(fmaf(0.125f, sacc[j][2], rh1 + sRw[(rq0+8)*33+kw0]));
      float e3 = __expf(fmaf(0.125f, sacc[j][3], rh1 + sRw[(rq0+8)*33+kw0+1]));
      rs0 += e0 + e1;
      rs1 += e2 + e3;
      float h0 = bf16hi(e0), h1 = bf16hi(e1), h2 = bf16hi(e2), h3 = bf16hi(e3);
      phi[j>>1][(j&1)*2]   = pack2(h0, h1);
      phi[j>>1][(j&1)*2+1] = pack2(h2, h3);
      plo[j>>1][(j&1)*2]   = pack2(e0-h0, e1-h1);
      plo[j>>1][(j&1)*2+1] = pack2(e2-h2, e3-h3);
    }

    #pragma unroll
    for (int j16 = 0; j16 < 4; j16++) {
      #pragma unroll
      for (int p = 0; p < 4; p++) {
        unsigned vh4[4], vl4[4];
        LDSM4(vh4, uVh + boffB + p*2304 + j16*32);
        LDSM4(vl4, uVh + 9216 + boffB + p*2304 + j16*32);
        #pragma unroll
        for (int h = 0; h < 2; h++) {
          const int nt = 2*p + h;
          unsigned b2[2] = { vh4[2*h], vh4[2*h+1] };
          unsigned l2[2] = { vl4[2*h], vl4[2*h+1] };
          mma16816(oacc[nt], phi[j16], b2);
          mma16816(oacc[nt], phi[j16], l2);
          mma16816(oacc[nt], plo[j16], b2);
        }
      }
    }
  }

  rs0 += __shfl_xor_sync(0xffffffffu, rs0, 1);
  rs0 += __shfl_xor_sync(0xffffffffu, rs0, 2);
  rs1 += __shfl_xor_sync(0xffffffffu, rs1, 1);
  rs1 += __shfl_xor_sync(0xffffffffu, rs1, 2);
  const float inv0 = 1.f / rs0, inv1 = 1.f / rs1;

  const int b = bh / HEADS, head = bh % HEADS;
  const int n0 = qt*128 + wq*16 + gr;
  #pragma unroll
  for (int nt = 0; nt < 8; nt++) {
    int d0 = nt*8 + tg*2;
    float o0 = oacc[nt][0]*inv0, o1 = oacc[nt][1]*inv0;
    float o2 = oacc[nt][2]*inv1, o3 = oacc[nt][3]*inv1;
    size_t b0 = ((size_t)(b*NTOK) + n0)*DIM + head*HD + d0;
    size_t b1 = ((size_t)(b*NTOK) + n0 + 8)*DIM + head*HD + d0;
    float h0 = bf16hi(o0), h1 = bf16hi(o1), h2 = bf16hi(o2), h3 = bf16hi(o3);
    *(unsigned*)&g_ah[b0] = pack2(h0, h1);
    *(unsigned*)&g_al[b0] = pack2(o0-h0, o1-h1);
    *(unsigned*)&g_ah[b1] = pack2(h2, h3);
    *(unsigned*)&g_al[b1] = pack2(o2-h2, o3-h3);
  }
}

extern "C" void kernel_launch(void* const* d_in, const int* in_sizes, int n_in,
                              void* d_out, int out_size) {
  const float* x      = (const float*)d_in[0];
  const float* qkv_w  = (const float*)d_in[1];
  const float* qkv_b  = (const float*)d_in[2];
  const float* proj_w = (const float*)d_in[3];
  const float* proj_b = (const float*)d_in[4];
  const float* rph    = (const float*)d_in[5];
  const float* rpw    = (const float*)d_in[6];
  float* out = (float*)d_out;

  cudaFuncSetAttribute(attn_kernel, cudaFuncAttributeMaxDynamicSharedMemorySize, 107520);
  cudaFuncSetAttribute(relpos_kernel, cudaFuncAttributeMaxDynamicSharedMemorySize, 49152);
  cudaFuncSetAttribute(gemm3bf16<0>, cudaFuncAttributeMaxDynamicSharedMemorySize, 61440);
  cudaFuncSetAttribute(gemm3bf16<1>, cudaFuncAttributeMaxDynamicSharedMemorySize, 61440);

  split_kernel<0><<<(MTOT*DIM + 255)/256, 256>>>(x, MTOT*DIM);
  split_kernel<1><<<(2304*DIM + 255)/256, 256>>>(qkv_w, 2304*DIM);
  split_kernel<2><<<(DIM*DIM + 255)/256, 256>>>(proj_w, DIM*DIM);

  gemm3bf16<0><<<dim3(36, 64), 256, 61440>>>(qkv_b, nullptr);
  relpos_kernel<<<dim3(16, 96), 256, 49152>>>(rph, rpw);
  attn_kernel<<<dim3(8, 96), 256, 107520>>>();
  gemm3bf16<1><<<dim3(12, 64), 256, 61440>>>(proj_b, out);
}